// round 13
// baseline (speedup 1.0000x reference)
#include <cuda_runtime.h>
#include <math.h>
#include <stdint.h>

// ---------------- problem constants ----------------
#define NNODE   20000
#define NPAD    20096
#define EDGES   640000
#define BB      256
#define DG      256
#define DH      512
#define DI      2048
#define RNK     512
#define NCLS    3
#define NGENE   6640
#define NGENE_PAD 6656
#define LN_EPS  1e-5f

// ---------------- scratch (device globals) ----------------
__device__ float g_x   [NPAD * DG];
__device__ float g_hln [NPAD * DG];
__device__ float g_agg [NPAD * DG];
__device__ int   g_deg [NNODE];
__device__ int   g_off [NNODE + 1];
__device__ int   g_cur [NNODE];
__device__ int   g_bsrc[EDGES];
__device__ float g_bw  [EDGES];
__device__ float g_pert[BB * DG];
__device__ float g_h   [BB * DH];
__device__ float g_z   [BB * DH];
__device__ float g_t   [BB * DI];
__device__ float g_part[4 * BB * DI];     // 2M floats: holds w1 x4 partials or w2 x16 partials
__device__ float g_proj[BB * NCLS * RNK];
__device__ float g_geneT[RNK * NGENE_PAD];
__device__ int   g_flag2[NNODE];
__device__ int   g_flag3[NNODE];
__device__ int   g_list2[NNODE];
__device__ int   g_list3[BB];
__device__ int   g_cnt2[1];
__device__ int   g_bsum[128];
__device__ int   g_bpre[128];

// ---------------- packed f32x2 + cp.async helpers ----------------
__device__ __forceinline__ void ffma2(unsigned long long &d, unsigned long long a, unsigned long long b) {
    asm("fma.rn.f32x2 %0, %1, %2, %0;" : "+l"(d) : "l"(a), "l"(b));
}
__device__ __forceinline__ unsigned long long pack2(float x, float y) {
    unsigned long long r;
    asm("mov.b64 %0, {%1, %2};" : "=l"(r) : "f"(x), "f"(y));
    return r;
}
__device__ __forceinline__ float lo2(unsigned long long v) {
    return __uint_as_float((unsigned)(v & 0xffffffffull));
}
__device__ __forceinline__ float hi2(unsigned long long v) {
    return __uint_as_float((unsigned)(v >> 32));
}
__device__ __forceinline__ uint32_t smem_u32(const void* p) {
    uint32_t a;
    asm("{ .reg .u64 t; cvta.to.shared.u64 t, %1; cvt.u32.u64 %0, t; }" : "=r"(a) : "l"(p));
    return a;
}
#define CP_ASYNC16(dst, src) \
    asm volatile("cp.async.cg.shared.global [%0], [%1], 16;" :: "r"(dst), "l"(src))
#define CP_COMMIT() asm volatile("cp.async.commit_group;" ::: "memory")
#define CP_WAIT1()  asm volatile("cp.async.wait_group 1;" ::: "memory")
#define CP_WAIT0()  asm volatile("cp.async.wait_group 0;" ::: "memory")

// ---------------- preprocessing kernels ----------------
__global__ void init_kernel(int* deg, int* flag2, int* flag3, int* cnt2) {
    int i = blockIdx.x * blockDim.x + threadIdx.x;
    if (i < NNODE) { deg[i] = 0; flag2[i] = 0; flag3[i] = 0; }
    if (i == 0) cnt2[0] = 0;
}
__global__ void flag_seed_kernel(const int* __restrict__ idx, int* flag2, int* flag3, int* list3) {
    int i = threadIdx.x;
    int id = idx[i];
    int safe = id < 0 ? 0 : id;
    flag3[safe] = 1;
    flag2[safe] = 1;
    list3[i] = safe;
}
__global__ void histflag_kernel(const int* __restrict__ ei, int* __restrict__ deg,
                                const int* __restrict__ flag3, int* __restrict__ flag2) {
    int e = blockIdx.x * blockDim.x + threadIdx.x;
    if (e < EDGES) {
        int d = ei[EDGES + e];
        atomicAdd(&deg[d], 1);
        if (flag3[d]) flag2[ei[e]] = 1;
    }
}
__global__ void scan1_kernel(const int* __restrict__ deg, int* __restrict__ off, int* __restrict__ bsum) {
    __shared__ int sh[256];
    int tid = threadIdx.x, i = blockIdx.x * 256 + tid;
    int v = (i < NNODE) ? deg[i] : 0;
    sh[tid] = v;
    __syncthreads();
    for (int o = 1; o < 256; o <<= 1) {
        int u = (tid >= o) ? sh[tid - o] : 0;
        __syncthreads();
        sh[tid] += u;
        __syncthreads();
    }
    if (i < NNODE) off[i + 1] = sh[tid];
    if (tid == 255) bsum[blockIdx.x] = sh[255];
}
__global__ void scan2_kernel(const int* __restrict__ bsum, int* __restrict__ bpre, int nb) {
    __shared__ int sh[128];
    int tid = threadIdx.x;
    int v = (tid < nb) ? bsum[tid] : 0;
    sh[tid] = v;
    __syncthreads();
    for (int o = 1; o < 128; o <<= 1) {
        int u = (tid >= o) ? sh[tid - o] : 0;
        __syncthreads();
        sh[tid] += u;
        __syncthreads();
    }
    if (tid < nb) bpre[tid] = sh[tid] - v;
}
__global__ void scan3_kernel(const int* __restrict__ deg, int* __restrict__ off,
                             const int* __restrict__ bpre, int* __restrict__ cur) {
    int i = blockIdx.x * blockDim.x + threadIdx.x;
    if (i < NNODE) {
        int o = off[i + 1] + bpre[i >> 8];
        off[i + 1] = o;
        cur[i] = o - deg[i];
        if (i == 0) off[0] = 0;
    }
}
__global__ void scatter_kernel(const int* __restrict__ ei, const float* __restrict__ ew,
                               int* __restrict__ cur, int* __restrict__ bsrc, float* __restrict__ bw) {
    int i = blockIdx.x * blockDim.x + threadIdx.x;
    if (i < EDGES) {
        int d = ei[EDGES + i];
        int p = atomicAdd(&cur[d], 1);
        bsrc[p] = ei[i];
        bw[p]   = ew[i];
    }
}
__global__ void compact_kernel(const int* __restrict__ flag2, int* __restrict__ list2,
                               int* __restrict__ cnt2) {
    int i = blockIdx.x * blockDim.x + threadIdx.x;
    if (i < NNODE && flag2[i]) {
        int p = atomicAdd(cnt2, 1);
        list2[p] = i;
    }
}
__global__ void tgene_kernel(const float* __restrict__ g, float* __restrict__ gt) {
    __shared__ float tb[32][33];
    int n0 = blockIdx.x * 32, r0 = blockIdx.y * 32;
    int tx = threadIdx.x, ty = threadIdx.y;
    for (int dy = 0; dy < 32; dy += 8) {
        int n = n0 + ty + dy;
        tb[ty + dy][tx] = (n < NGENE) ? g[(size_t)n * RNK + r0 + tx] : 0.f;
    }
    __syncthreads();
    for (int dy = 0; dy < 32; dy += 8)
        gt[(size_t)(r0 + ty + dy) * NGENE_PAD + n0 + tx] = tb[tx][ty + dy];
}

// ---------------- LN / agg / misc ----------------
__global__ void ln_kernel(const float* __restrict__ x, const float* __restrict__ s,
                          const float* __restrict__ b, float* __restrict__ y,
                          int rows, int D, const int* __restrict__ flag) {
    int wid = threadIdx.x >> 5, lane = threadIdx.x & 31;
    int row = blockIdx.x * (blockDim.x >> 5) + wid;
    if (row >= rows) return;
    if (flag && !flag[row]) return;
    const float4* xr = (const float4*)(x + (size_t)row * D);
    int nf = D >> 7;
    float4 r[4];
    float sum = 0.f;
    for (int t = 0; t < nf; ++t) {
        r[t] = xr[lane + 32 * t];
        sum += r[t].x + r[t].y + r[t].z + r[t].w;
    }
    for (int o = 16; o > 0; o >>= 1) sum += __shfl_xor_sync(0xffffffffu, sum, o);
    float mu = sum / (float)D;
    float vs = 0.f;
    for (int t = 0; t < nf; ++t) {
        float dx = r[t].x - mu, dy = r[t].y - mu, dz = r[t].z - mu, dw = r[t].w - mu;
        vs += dx * dx + dy * dy + dz * dz + dw * dw;
    }
    for (int o = 16; o > 0; o >>= 1) vs += __shfl_xor_sync(0xffffffffu, vs, o);
    float w = rsqrtf(vs / (float)D + LN_EPS);
    float4* yr = (float4*)(y + (size_t)row * D);
    for (int t = 0; t < nf; ++t) {
        int col = (lane + 32 * t) * 4;
        float4 o4;
        o4.x = (r[t].x - mu) * w * s[col + 0] + b[col + 0];
        o4.y = (r[t].y - mu) * w * s[col + 1] + b[col + 1];
        o4.z = (r[t].z - mu) * w * s[col + 2] + b[col + 2];
        o4.w = (r[t].w - mu) * w * s[col + 3] + b[col + 3];
        yr[lane + 32 * t] = o4;
    }
}
__global__ void agg_kernel(const float* __restrict__ hln, float* __restrict__ agg,
                           const int* __restrict__ off, const int* __restrict__ bsrc,
                           const float* __restrict__ bw, const int* __restrict__ flag) {
    int wid = threadIdx.x >> 5, lane = threadIdx.x & 31;
    int node = blockIdx.x * (blockDim.x >> 5) + wid;
    if (node >= NNODE) return;
    if (flag && !flag[node]) return;
    int st = off[node], en = off[node + 1];
    float4 a0 = make_float4(0, 0, 0, 0), a1 = make_float4(0, 0, 0, 0);
    for (int j = st; j < en; ++j) {
        int s = bsrc[j];
        float w = bw[j];
        const float4* r = (const float4*)(hln + s * DG);
        float4 v0 = r[lane], v1 = r[lane + 32];
        a0.x = fmaf(w, v0.x, a0.x); a0.y = fmaf(w, v0.y, a0.y);
        a0.z = fmaf(w, v0.z, a0.z); a0.w = fmaf(w, v0.w, a0.w);
        a1.x = fmaf(w, v1.x, a1.x); a1.y = fmaf(w, v1.y, a1.y);
        a1.z = fmaf(w, v1.z, a1.z); a1.w = fmaf(w, v1.w, a1.w);
    }
    float4* o = (float4*)(agg + node * DG);
    o[lane] = a0;
    o[lane + 32] = a1;
}
// vectorized split-K reduce. mode 0: dst = b + sum ; 2: dst = gelu(b + sum)
__global__ void reduce4_kernel(float4* __restrict__ dst, const float4* __restrict__ part,
                               const float4* __restrict__ bias, int S, int total4, int N4, int mode) {
    int i = blockIdx.x * blockDim.x + threadIdx.x;
    if (i >= total4) return;
    float4 v = bias[i % N4];
    for (int z = 0; z < S; ++z) {
        float4 p = part[(size_t)z * total4 + i];
        v.x += p.x; v.y += p.y; v.z += p.z; v.w += p.w;
    }
    if (mode == 2) {
        v.x = 0.5f * v.x * (1.f + erff(v.x * 0.70710678118654752f));
        v.y = 0.5f * v.y * (1.f + erff(v.y * 0.70710678118654752f));
        v.z = 0.5f * v.z * (1.f + erff(v.z * 0.70710678118654752f));
        v.w = 0.5f * v.w * (1.f + erff(v.w * 0.70710678118654752f));
    }
    dst[i] = v;
}
// fused split-K reduce + residual add + (optional) LayerNorm. Rows = BB, width DH.
__global__ void reduce_ln_kernel(float* __restrict__ h, const float* __restrict__ part,
                                 const float* __restrict__ b2, const float* __restrict__ lns,
                                 const float* __restrict__ lnb, float* __restrict__ z, int S) {
    int wid = threadIdx.x >> 5, lane = threadIdx.x & 31;
    int row = blockIdx.x * (blockDim.x >> 5) + wid;
    if (row >= BB) return;
    float4 r[4];
    const float4* hr = (const float4*)(h + (size_t)row * DH);
#pragma unroll
    for (int t = 0; t < 4; ++t) {
        int col4 = lane + 32 * t;
        float4 v = hr[col4];
        int colb = col4 * 4;
        float s0 = b2[colb], s1 = b2[colb + 1], s2 = b2[colb + 2], s3 = b2[colb + 3];
        for (int zz = 0; zz < S; ++zz) {
            const float4 p = *(const float4*)(part + (size_t)zz * BB * DH + (size_t)row * DH + colb);
            s0 += p.x; s1 += p.y; s2 += p.z; s3 += p.w;
        }
        v.x += s0; v.y += s1; v.z += s2; v.w += s3;
        r[t] = v;
    }
    float4* hw = (float4*)(h + (size_t)row * DH);
#pragma unroll
    for (int t = 0; t < 4; ++t) hw[lane + 32 * t] = r[t];
    if (!lns) return;
    float sum = 0.f;
#pragma unroll
    for (int t = 0; t < 4; ++t) sum += r[t].x + r[t].y + r[t].z + r[t].w;
    for (int o = 16; o > 0; o >>= 1) sum += __shfl_xor_sync(0xffffffffu, sum, o);
    float mu = sum / (float)DH;
    float vs = 0.f;
#pragma unroll
    for (int t = 0; t < 4; ++t) {
        float dx = r[t].x - mu, dy = r[t].y - mu, dz = r[t].z - mu, dw = r[t].w - mu;
        vs += dx * dx + dy * dy + dz * dz + dw * dw;
    }
    for (int o = 16; o > 0; o >>= 1) vs += __shfl_xor_sync(0xffffffffu, vs, o);
    float w = rsqrtf(vs / (float)DH + LN_EPS);
    float4* zr = (float4*)(z + (size_t)row * DH);
#pragma unroll
    for (int t = 0; t < 4; ++t) {
        int col = (lane + 32 * t) * 4;
        float4 o4;
        o4.x = (r[t].x - mu) * w * lns[col + 0] + lnb[col + 0];
        o4.y = (r[t].y - mu) * w * lns[col + 1] + lnb[col + 1];
        o4.z = (r[t].z - mu) * w * lns[col + 2] + lnb[col + 2];
        o4.w = (r[t].w - mu) * w * lns[col + 3] + lnb[col + 3];
        zr[lane + 32 * t] = o4;
    }
}

// ---------------- GEMM: cp.async 3-stage pipeline, 128x64 tile, BK=16, 128 thr, f32x2 ----
enum { EPI_NONE = 0, EPI_BIAS = 1, EPI_RELU_RES = 2 };

__global__ void __launch_bounds__(128) gemmp_kernel(
    const float* __restrict__ A, const float* __restrict__ B,
    const float* __restrict__ bias, const float* __restrict__ res,
    float* __restrict__ C, const int* __restrict__ rowsA, const int* __restrict__ rowsC,
    const int* __restrict__ cntp, const int* __restrict__ oovIdx, const float* __restrict__ oovEmb,
    int M, int Nb, int Nout, int K, int kChunk, int epi)
{
    __shared__ __align__(16) float As[3][128][16];
    __shared__ __align__(16) float Bs[3][16][64];
    int Meff = cntp ? *cntp : M;
    int t = threadIdx.x;
    int m0 = blockIdx.y * 128;
    if (m0 >= Meff) return;
    int n0 = blockIdx.x * 64;
    int ks = blockIdx.z * kChunk;
    int ke = ks + kChunk; if (ke > K) ke = K;
    int nkb = (ke - ks) >> 4;

    uint32_t sA = smem_u32(As);
    uint32_t sB = smem_u32(Bs);

    int mj0 = t >> 2, cA = t & 3;
    const float* aSrc[4];
    uint32_t aDst[4];
#pragma unroll
    for (int j = 0; j < 4; ++j) {
        int ml = 32 * j + mj0;
        int lm = m0 + ml;
        int gm;
        if (rowsA) gm = rowsA[lm < Meff ? lm : 0];
        else       gm = (lm < M) ? lm : 0;
        aSrc[j] = A + (size_t)gm * K + ks + 4 * cA;
        int cs = cA ^ ((ml >> 3) & 3);
        aDst[j] = sA + (uint32_t)(ml * 64 + cs * 16);
    }
    const float* bSrc[2];
    uint32_t bDst[2];
#pragma unroll
    for (int j = 0; j < 2; ++j) {
        int id = t + 128 * j;
        int kr = id >> 4, cb = id & 15;
        bSrc[j] = B + (size_t)(ks + kr) * Nb + n0 + 4 * cb;
        bDst[j] = sB + (uint32_t)(kr * 256 + cb * 16);
    }

    unsigned long long acc[8][4];
#pragma unroll
    for (int i = 0; i < 8; ++i)
#pragma unroll
        for (int j = 0; j < 4; ++j) acc[i][j] = 0ull;

    int gtw = (t >> 3) & 3;
    int ty8 = (t >> 3) * 8, tx8 = (t & 7) * 8;
    int fo[4];
#pragma unroll
    for (int c = 0; c < 4; ++c) fo[c] = 4 * (c ^ gtw);

    {
#pragma unroll
        for (int j = 0; j < 4; ++j) CP_ASYNC16(aDst[j], aSrc[j]);
#pragma unroll
        for (int j = 0; j < 2; ++j) CP_ASYNC16(bDst[j], bSrc[j]);
        CP_COMMIT();
        if (nkb > 1) {
#pragma unroll
            for (int j = 0; j < 4; ++j) CP_ASYNC16(aDst[j] + 8192u, aSrc[j] + 16);
#pragma unroll
            for (int j = 0; j < 2; ++j) CP_ASYNC16(bDst[j] + 4096u, bSrc[j] + (size_t)16 * Nb);
            CP_COMMIT();
        }
    }

    for (int i = 0; i < nkb; ++i) {
        if (i + 1 < nkb) { CP_WAIT1(); } else { CP_WAIT0(); }
        __syncthreads();
        int nx = i + 2;
        if (nx < nkb) {
            int st = nx % 3;
            uint32_t so = (uint32_t)st * 8192u, sob = (uint32_t)st * 4096u;
            int kof = nx << 4;
#pragma unroll
            for (int j = 0; j < 4; ++j) CP_ASYNC16(aDst[j] + so, aSrc[j] + kof);
#pragma unroll
            for (int j = 0; j < 2; ++j) CP_ASYNC16(bDst[j] + sob, bSrc[j] + (size_t)kof * Nb);
            CP_COMMIT();
        }
        int s = i % 3;
        const float (*Asr)[16] = As[s];
        const float (*Bsr)[64] = Bs[s];
#pragma unroll
        for (int kk = 0; kk < 16; ++kk) {
            int fs = fo[kk >> 2] + (kk & 3);
            unsigned long long ad[8], bd[4];
#pragma unroll
            for (int i8 = 0; i8 < 8; ++i8) {
                float av = Asr[ty8 + i8][fs];
                ad[i8] = pack2(av, av);
            }
#pragma unroll
            for (int j = 0; j < 4; ++j)
                bd[j] = *(const unsigned long long*)&Bsr[kk][tx8 + 2 * j];
#pragma unroll
            for (int i8 = 0; i8 < 8; ++i8)
#pragma unroll
                for (int j = 0; j < 4; ++j)
                    ffma2(acc[i8][j], ad[i8], bd[j]);
        }
    }

    float* Cz = C + (size_t)blockIdx.z * M * Nout;
    bool nfull = (n0 + 64 <= Nout);
#pragma unroll
    for (int i8 = 0; i8 < 8; ++i8) {
        int lm = m0 + ty8 + i8;
        if (lm >= Meff) continue;
        int gr = rowsC ? rowsC[lm] : lm;
        float v[8];
#pragma unroll
        for (int j = 0; j < 4; ++j) {
            v[2 * j]     = lo2(acc[i8][j]);
            v[2 * j + 1] = hi2(acc[i8][j]);
        }
        int gn0 = n0 + tx8;
        if (epi == EPI_RELU_RES) {
#pragma unroll
            for (int j = 0; j < 8; ++j) {
                float bi = bias[gn0 + j];
                float rv = res[(size_t)gr * Nout + gn0 + j];
                v[j] = fmaxf(v[j] + bi, 0.f) + rv;
            }
        } else if (epi == EPI_BIAS) {
#pragma unroll
            for (int j = 0; j < 8; ++j) v[j] += bias[gn0 + j];
        }
        if (oovIdx && oovIdx[lm] < 0) {
#pragma unroll
            for (int j = 0; j < 8; ++j) v[j] = oovEmb[gn0 + j];
        }
        float* crow = Cz + (size_t)gr * Nout;
        if (nfull) {
            *(float4*)(crow + gn0)     = make_float4(v[0], v[1], v[2], v[3]);
            *(float4*)(crow + gn0 + 4) = make_float4(v[4], v[5], v[6], v[7]);
        } else {
#pragma unroll
            for (int j = 0; j < 8; ++j)
                if (gn0 + j < Nout) crow[gn0 + j] = v[j];
        }
    }
}

// ---------------- launch ----------------
extern "C" void kernel_launch(void* const* d_in, const int* in_sizes, int n_in,
                              void* d_out, int out_size) {
    const int*   node_indices = (const int*)d_in[0];
    const int*   edge_index   = (const int*)d_in[1];
    const float* edge_weight  = (const float*)d_in[2];
    const float* partial_emb  = (const float*)d_in[3];
    const float* oov_emb      = (const float*)d_in[4];
    const float* gnn_ln_s     = (const float*)d_in[5];
    const float* gnn_ln_b     = (const float*)d_in[6];
    const float* gnn_w        = (const float*)d_in[7];
    const float* gnn_b        = (const float*)d_in[8];
    const float* post_w       = (const float*)d_in[9];
    const float* post_b       = (const float*)d_in[10];
    const float* pin_w        = (const float*)d_in[11];
    const float* pin_b        = (const float*)d_in[12];
    const float* blk_ln_s     = (const float*)d_in[13];
    const float* blk_ln_b     = (const float*)d_in[14];
    const float* blk_w1       = (const float*)d_in[15];
    const float* blk_b1       = (const float*)d_in[16];
    const float* blk_w2       = (const float*)d_in[17];
    const float* blk_b2       = (const float*)d_in[18];
    const float* pout_w       = (const float*)d_in[19];
    const float* pout_b       = (const float*)d_in[20];
    const float* gene         = (const float*)d_in[21];
    float*       out          = (float*)d_out;

    static float *p_x = nullptr, *p_hln, *p_agg, *p_bw, *p_pert, *p_h, *p_z, *p_t, *p_part, *p_proj, *p_geneT;
    static int   *p_deg, *p_off, *p_cur, *p_bsrc;
    static int   *p_flag2, *p_flag3, *p_list2, *p_list3, *p_cnt2, *p_bsum, *p_bpre;
    static cudaStream_t sB = nullptr, sC = nullptr;
    static cudaEvent_t  e0, e1, eCSR, eGene;
    if (!p_x) {
        cudaGetSymbolAddress((void**)&p_x,    g_x);
        cudaGetSymbolAddress((void**)&p_hln,  g_hln);
        cudaGetSymbolAddress((void**)&p_agg,  g_agg);
        cudaGetSymbolAddress((void**)&p_bw,   g_bw);
        cudaGetSymbolAddress((void**)&p_pert, g_pert);
        cudaGetSymbolAddress((void**)&p_h,    g_h);
        cudaGetSymbolAddress((void**)&p_z,    g_z);
        cudaGetSymbolAddress((void**)&p_t,    g_t);
        cudaGetSymbolAddress((void**)&p_part, g_part);
        cudaGetSymbolAddress((void**)&p_proj, g_proj);
        cudaGetSymbolAddress((void**)&p_geneT, g_geneT);
        cudaGetSymbolAddress((void**)&p_deg,  g_deg);
        cudaGetSymbolAddress((void**)&p_off,  g_off);
        cudaGetSymbolAddress((void**)&p_cur,  g_cur);
        cudaGetSymbolAddress((void**)&p_bsrc, g_bsrc);
        cudaGetSymbolAddress((void**)&p_flag2, g_flag2);
        cudaGetSymbolAddress((void**)&p_flag3, g_flag3);
        cudaGetSymbolAddress((void**)&p_list2, g_list2);
        cudaGetSymbolAddress((void**)&p_list3, g_list3);
        cudaGetSymbolAddress((void**)&p_cnt2,  g_cnt2);
        cudaGetSymbolAddress((void**)&p_bsum,  g_bsum);
        cudaGetSymbolAddress((void**)&p_bpre,  g_bpre);
        cudaStreamCreateWithFlags(&sB, cudaStreamNonBlocking);
        cudaStreamCreateWithFlags(&sC, cudaStreamNonBlocking);
        cudaEventCreateWithFlags(&e0,    cudaEventDisableTiming);
        cudaEventCreateWithFlags(&e1,    cudaEventDisableTiming);
        cudaEventCreateWithFlags(&eCSR,  cudaEventDisableTiming);
        cudaEventCreateWithFlags(&eGene, cudaEventDisableTiming);
    }

    const int NB = (NNODE + 255) / 256;
    const int LNG = (NNODE + 7) / 8;

    cudaEventRecord(e0, 0);

    // side C: gene transpose
    cudaStreamWaitEvent(sC, e0, 0);
    tgene_kernel<<<dim3(NGENE_PAD / 32, RNK / 32), dim3(32, 8), 0, sC>>>(gene, p_geneT);
    cudaEventRecord(eGene, sC);

    // main: init + seed, then fork CSR build to side B
    init_kernel<<<NB, 256>>>(p_deg, p_flag2, p_flag3, p_cnt2);
    flag_seed_kernel<<<1, BB>>>(node_indices, p_flag2, p_flag3, p_list3);
    cudaEventRecord(e1, 0);

    cudaStreamWaitEvent(sB, e1, 0);
    histflag_kernel<<<(EDGES + 255) / 256, 256, 0, sB>>>(edge_index, p_deg, p_flag3, p_flag2);
    scan1_kernel<<<NB, 256, 0, sB>>>(p_deg, p_off, p_bsum);
    scan2_kernel<<<1, 128, 0, sB>>>(p_bsum, p_bpre, NB);
    scan3_kernel<<<NB, 256, 0, sB>>>(p_deg, p_off, p_bpre, p_cur);
    scatter_kernel<<<(EDGES + 255) / 256, 256, 0, sB>>>(edge_index, edge_weight, p_cur, p_bsrc, p_bw);
    compact_kernel<<<NB, 256, 0, sB>>>(p_flag2, p_list2, p_cnt2);
    cudaEventRecord(eCSR, sB);

    // main (concurrent with CSR): LN layer 0 directly from partial_emb
    ln_kernel<<<LNG, 256>>>(partial_emb, gnn_ln_s, gnn_ln_b, p_hln, NNODE, DG, nullptr);

    cudaStreamWaitEvent(0, eCSR, 0);

    // ---- GNN layer 0: dense (residual = partial_emb) ----
    agg_kernel<<<(NNODE + 7) / 8, 256>>>(p_hln, p_agg, p_off, p_bsrc, p_bw, nullptr);
    gemmp_kernel<<<dim3(DG / 64, (NNODE + 127) / 128, 1), 128>>>(
        p_agg, gnn_w, gnn_b, partial_emb, p_x, nullptr, nullptr, nullptr, nullptr, nullptr,
        NNODE, DG, DG, DG, DG, EPI_RELU_RES);

    // ---- GNN layer 1: frontier F2 ----
    ln_kernel<<<LNG, 256>>>(p_x, gnn_ln_s + DG, gnn_ln_b + DG, p_hln, NNODE, DG, nullptr);
    agg_kernel<<<(NNODE + 7) / 8, 256>>>(p_hln, p_agg, p_off, p_bsrc, p_bw, p_flag2);
    gemmp_kernel<<<dim3(DG / 64, (NNODE + 127) / 128, 1), 128>>>(
        p_agg, gnn_w + (size_t)1 * DG * DG, gnn_b + DG, p_x, p_x, p_list2, p_list2, p_cnt2,
        nullptr, nullptr, NNODE, DG, DG, DG, DG, EPI_RELU_RES);

    // ---- GNN layer 2: frontier F3 (LN restricted to F2) ----
    ln_kernel<<<LNG, 256>>>(p_x, gnn_ln_s + 2 * DG, gnn_ln_b + 2 * DG, p_hln, NNODE, DG, p_flag2);
    agg_kernel<<<(NNODE + 7) / 8, 256>>>(p_hln, p_agg, p_off, p_bsrc, p_bw, p_flag3);
    gemmp_kernel<<<dim3(DG / 64, BB / 128, 1), 128>>>(
        p_agg, gnn_w + (size_t)2 * DG * DG, gnn_b + 2 * DG, p_x, p_x, p_list3, p_list3, nullptr,
        nullptr, nullptr, BB, DG, DG, DG, DG, EPI_RELU_RES);

    // ---- post_mp: gather via list3, oov replacement fused in epilogue ----
    gemmp_kernel<<<dim3(DG / 64, BB / 128, 1), 128>>>(
        p_x, post_w, post_b, nullptr, p_pert, p_list3, nullptr, nullptr,
        node_indices, oov_emb, BB, DG, DG, DG, DG, EPI_BIAS);

    // ---- proj_in ----
    gemmp_kernel<<<dim3(DH / 64, BB / 128, 1), 128>>>(
        p_pert, pin_w, pin_b, nullptr, p_h, nullptr, nullptr, nullptr, nullptr, nullptr,
        BB, DH, DH, DG, DG, EPI_BIAS);

    // ---- 6 residual MLP blocks ----
    ln_kernel<<<BB / 8, 256>>>(p_h, blk_ln_s, blk_ln_b, p_z, BB, DH, nullptr);
    for (int i = 0; i < 6; ++i) {
        gemmp_kernel<<<dim3(DI / 64, BB / 128, 4), 128>>>(
            p_z, blk_w1 + (size_t)i * DH * DI, nullptr, nullptr, p_part,
            nullptr, nullptr, nullptr, nullptr, nullptr, BB, DI, DI, DH, DH / 4, EPI_NONE);
        reduce4_kernel<<<(BB * DI / 4 + 255) / 256, 256>>>(
            (float4*)p_t, (const float4*)p_part, (const float4*)(blk_b1 + i * DI),
            4, BB * DI / 4, DI / 4, 2);
        // w2: split-K x16 -> 256 blocks (full chip fill)
        gemmp_kernel<<<dim3(DH / 64, BB / 128, 16), 128>>>(
            p_t, blk_w2 + (size_t)i * DI * DH, nullptr, nullptr, p_part,
            nullptr, nullptr, nullptr, nullptr, nullptr, BB, DH, DH, DI, DI / 16, EPI_NONE);
        const float* lns = (i < 5) ? blk_ln_s + (i + 1) * DH : nullptr;
        const float* lnb = (i < 5) ? blk_ln_b + (i + 1) * DH : nullptr;
        reduce_ln_kernel<<<BB / 8, 256>>>(p_h, p_part, blk_b2 + i * DH, lns, lnb, p_z, 16);
    }

    // ---- proj_out (split-K x4 -> 192 blocks) ----
    gemmp_kernel<<<dim3((NCLS * RNK) / 64, BB / 128, 4), 128>>>(
        p_h, pout_w, nullptr, nullptr, p_part, nullptr, nullptr, nullptr, nullptr, nullptr,
        BB, NCLS * RNK, NCLS * RNK, DH, DH / 4, EPI_NONE);
    reduce4_kernel<<<(BB * NCLS * RNK / 4 + 255) / 256, 256>>>(
        (float4*)p_proj, (const float4*)p_part, (const float4*)pout_b,
        4, BB * NCLS * RNK / 4, NCLS * RNK / 4, 0);

    // ---- logits (wait for geneT) ----
    cudaStreamWaitEvent(0, eGene, 0);
    gemmp_kernel<<<dim3(NGENE_PAD / 64, (BB * NCLS) / 128, 1), 128>>>(
        p_proj, p_geneT, nullptr, nullptr, out, nullptr, nullptr, nullptr, nullptr, nullptr,
        BB * NCLS, NGENE_PAD, NGENE, RNK, RNK, EPI_NONE);
}

// round 15
// speedup vs baseline: 1.0043x; 1.0043x over previous
#include <cuda_runtime.h>
#include <math.h>
#include <stdint.h>

// ---------------- problem constants ----------------
#define NNODE   20000
#define NPAD    20096
#define EDGES   640000
#define BB      256
#define DG      256
#define DH      512
#define DI      2048
#define RNK     512
#define NCLS    3
#define NGENE   6640
#define NGENE_PAD 6656
#define LN_EPS  1e-5f

// ---------------- scratch (device globals) ----------------
__device__ float g_x   [NPAD * DG];
__device__ float g_hln [NPAD * DG];
__device__ float g_agg [NPAD * DG];
__device__ int   g_deg [NNODE];
__device__ int   g_off [NNODE + 1];
__device__ int   g_cur [NNODE];
__device__ int   g_bsrc[EDGES];
__device__ float g_bw  [EDGES];
__device__ float g_pert[BB * DG];
__device__ float g_h   [BB * DH];
__device__ float g_z   [BB * DH];
__device__ float g_t   [BB * DI];
__device__ float g_part[4 * BB * DI];
__device__ float g_proj[BB * NCLS * RNK];
__device__ float g_geneT[RNK * NGENE_PAD];
__device__ int   g_flag2[NNODE];
__device__ int   g_flag3[NNODE];
__device__ int   g_list2[NNODE];
__device__ int   g_list3[BB];
__device__ int   g_cnt2[1];
__device__ int   g_bsum[128];
__device__ int   g_bpre[128];

// ---------------- packed f32x2 + cp.async helpers ----------------
__device__ __forceinline__ void ffma2(unsigned long long &d, unsigned long long a, unsigned long long b) {
    asm("fma.rn.f32x2 %0, %1, %2, %0;" : "+l"(d) : "l"(a), "l"(b));
}
__device__ __forceinline__ unsigned long long pack2(float x, float y) {
    unsigned long long r;
    asm("mov.b64 %0, {%1, %2};" : "=l"(r) : "f"(x), "f"(y));
    return r;
}
__device__ __forceinline__ float lo2(unsigned long long v) {
    return __uint_as_float((unsigned)(v & 0xffffffffull));
}
__device__ __forceinline__ float hi2(unsigned long long v) {
    return __uint_as_float((unsigned)(v >> 32));
}
__device__ __forceinline__ uint32_t smem_u32(const void* p) {
    uint32_t a;
    asm("{ .reg .u64 t; cvta.to.shared.u64 t, %1; cvt.u32.u64 %0, t; }" : "=r"(a) : "l"(p));
    return a;
}
#define CP_ASYNC16(dst, src) \
    asm volatile("cp.async.cg.shared.global [%0], [%1], 16;" :: "r"(dst), "l"(src))
#define CP_COMMIT() asm volatile("cp.async.commit_group;" ::: "memory")
#define CP_WAIT1()  asm volatile("cp.async.wait_group 1;" ::: "memory")
#define CP_WAIT0()  asm volatile("cp.async.wait_group 0;" ::: "memory")

// ---------------- preprocessing kernels ----------------
__global__ void init_kernel(int* deg, int* flag2, int* flag3, int* cnt2) {
    int i = blockIdx.x * blockDim.x + threadIdx.x;
    if (i < NNODE) { deg[i] = 0; flag2[i] = 0; flag3[i] = 0; }
    if (i == 0) cnt2[0] = 0;
}
__global__ void flag_seed_kernel(const int* __restrict__ idx, int* flag2, int* flag3, int* list3) {
    int i = threadIdx.x;
    int id = idx[i];
    int safe = id < 0 ? 0 : id;
    flag3[safe] = 1;
    flag2[safe] = 1;
    list3[i] = safe;
}
__global__ void histflag_kernel(const int* __restrict__ ei, int* __restrict__ deg,
                                const int* __restrict__ flag3, int* __restrict__ flag2) {
    int e = blockIdx.x * blockDim.x + threadIdx.x;
    if (e < EDGES) {
        int d = ei[EDGES + e];
        atomicAdd(&deg[d], 1);
        if (flag3[d]) flag2[ei[e]] = 1;
    }
}
__global__ void scan1_kernel(const int* __restrict__ deg, int* __restrict__ off, int* __restrict__ bsum) {
    __shared__ int sh[256];
    int tid = threadIdx.x, i = blockIdx.x * 256 + tid;
    int v = (i < NNODE) ? deg[i] : 0;
    sh[tid] = v;
    __syncthreads();
    for (int o = 1; o < 256; o <<= 1) {
        int u = (tid >= o) ? sh[tid - o] : 0;
        __syncthreads();
        sh[tid] += u;
        __syncthreads();
    }
    if (i < NNODE) off[i + 1] = sh[tid];
    if (tid == 255) bsum[blockIdx.x] = sh[255];
}
__global__ void scan2_kernel(const int* __restrict__ bsum, int* __restrict__ bpre, int nb) {
    __shared__ int sh[128];
    int tid = threadIdx.x;
    int v = (tid < nb) ? bsum[tid] : 0;
    sh[tid] = v;
    __syncthreads();
    for (int o = 1; o < 128; o <<= 1) {
        int u = (tid >= o) ? sh[tid - o] : 0;
        __syncthreads();
        sh[tid] += u;
        __syncthreads();
    }
    if (tid < nb) bpre[tid] = sh[tid] - v;
}
__global__ void scan3_kernel(const int* __restrict__ deg, int* __restrict__ off,
                             const int* __restrict__ bpre, int* __restrict__ cur) {
    int i = blockIdx.x * blockDim.x + threadIdx.x;
    if (i < NNODE) {
        int o = off[i + 1] + bpre[i >> 8];
        off[i + 1] = o;
        cur[i] = o - deg[i];
        if (i == 0) off[0] = 0;
    }
}
__global__ void scatter_kernel(const int* __restrict__ ei, const float* __restrict__ ew,
                               int* __restrict__ cur, int* __restrict__ bsrc, float* __restrict__ bw) {
    int i = blockIdx.x * blockDim.x + threadIdx.x;
    if (i < EDGES) {
        int d = ei[EDGES + i];
        int p = atomicAdd(&cur[d], 1);
        bsrc[p] = ei[i];
        bw[p]   = ew[i];
    }
}
__global__ void compact_kernel(const int* __restrict__ flag2, int* __restrict__ list2,
                               int* __restrict__ cnt2) {
    int i = blockIdx.x * blockDim.x + threadIdx.x;
    if (i < NNODE && flag2[i]) {
        int p = atomicAdd(cnt2, 1);
        list2[p] = i;
    }
}
__global__ void tgene_kernel(const float* __restrict__ g, float* __restrict__ gt) {
    __shared__ float tb[32][33];
    int n0 = blockIdx.x * 32, r0 = blockIdx.y * 32;
    int tx = threadIdx.x, ty = threadIdx.y;
    for (int dy = 0; dy < 32; dy += 8) {
        int n = n0 + ty + dy;
        tb[ty + dy][tx] = (n < NGENE) ? g[(size_t)n * RNK + r0 + tx] : 0.f;
    }
    __syncthreads();
    for (int dy = 0; dy < 32; dy += 8)
        gt[(size_t)(r0 + ty + dy) * NGENE_PAD + n0 + tx] = tb[tx][ty + dy];
}

// ---------------- LN / agg / misc ----------------
__global__ void ln_kernel(const float* __restrict__ x, const float* __restrict__ s,
                          const float* __restrict__ b, float* __restrict__ y,
                          int rows, int D, const int* __restrict__ flag) {
    int wid = threadIdx.x >> 5, lane = threadIdx.x & 31;
    int row = blockIdx.x * (blockDim.x >> 5) + wid;
    if (row >= rows) return;
    if (flag && !flag[row]) return;
    const float4* xr = (const float4*)(x + (size_t)row * D);
    int nf = D >> 7;
    float4 r[4];
    float sum = 0.f;
    for (int t = 0; t < nf; ++t) {
        r[t] = xr[lane + 32 * t];
        sum += r[t].x + r[t].y + r[t].z + r[t].w;
    }
    for (int o = 16; o > 0; o >>= 1) sum += __shfl_xor_sync(0xffffffffu, sum, o);
    float mu = sum / (float)D;
    float vs = 0.f;
    for (int t = 0; t < nf; ++t) {
        float dx = r[t].x - mu, dy = r[t].y - mu, dz = r[t].z - mu, dw = r[t].w - mu;
        vs += dx * dx + dy * dy + dz * dz + dw * dw;
    }
    for (int o = 16; o > 0; o >>= 1) vs += __shfl_xor_sync(0xffffffffu, vs, o);
    float w = rsqrtf(vs / (float)D + LN_EPS);
    float4* yr = (float4*)(y + (size_t)row * D);
    for (int t = 0; t < nf; ++t) {
        int col = (lane + 32 * t) * 4;
        float4 o4;
        o4.x = (r[t].x - mu) * w * s[col + 0] + b[col + 0];
        o4.y = (r[t].y - mu) * w * s[col + 1] + b[col + 1];
        o4.z = (r[t].z - mu) * w * s[col + 2] + b[col + 2];
        o4.w = (r[t].w - mu) * w * s[col + 3] + b[col + 3];
        yr[lane + 32 * t] = o4;
    }
}
__global__ void agg_kernel(const float* __restrict__ hln, float* __restrict__ agg,
                           const int* __restrict__ off, const int* __restrict__ bsrc,
                           const float* __restrict__ bw, const int* __restrict__ flag) {
    int wid = threadIdx.x >> 5, lane = threadIdx.x & 31;
    int node = blockIdx.x * (blockDim.x >> 5) + wid;
    if (node >= NNODE) return;
    if (flag && !flag[node]) return;
    int st = off[node], en = off[node + 1];
    float4 a0 = make_float4(0, 0, 0, 0), a1 = make_float4(0, 0, 0, 0);
    for (int j = st; j < en; ++j) {
        int s = bsrc[j];
        float w = bw[j];
        const float4* r = (const float4*)(hln + s * DG);
        float4 v0 = r[lane], v1 = r[lane + 32];
        a0.x = fmaf(w, v0.x, a0.x); a0.y = fmaf(w, v0.y, a0.y);
        a0.z = fmaf(w, v0.z, a0.z); a0.w = fmaf(w, v0.w, a0.w);
        a1.x = fmaf(w, v1.x, a1.x); a1.y = fmaf(w, v1.y, a1.y);
        a1.z = fmaf(w, v1.z, a1.z); a1.w = fmaf(w, v1.w, a1.w);
    }
    float4* o = (float4*)(agg + node * DG);
    o[lane] = a0;
    o[lane + 32] = a1;
}
// vectorized split-K reduce. mode 0: dst = b + sum ; 2: dst = gelu(b + sum)
__global__ void reduce4_kernel(float4* __restrict__ dst, const float4* __restrict__ part,
                               const float4* __restrict__ bias, int S, int total4, int N4, int mode) {
    int i = blockIdx.x * blockDim.x + threadIdx.x;
    if (i >= total4) return;
    float4 v = bias[i % N4];
    for (int z = 0; z < S; ++z) {
        float4 p = part[(size_t)z * total4 + i];
        v.x += p.x; v.y += p.y; v.z += p.z; v.w += p.w;
    }
    if (mode == 2) {
        v.x = 0.5f * v.x * (1.f + erff(v.x * 0.70710678118654752f));
        v.y = 0.5f * v.y * (1.f + erff(v.y * 0.70710678118654752f));
        v.z = 0.5f * v.z * (1.f + erff(v.z * 0.70710678118654752f));
        v.w = 0.5f * v.w * (1.f + erff(v.w * 0.70710678118654752f));
    }
    dst[i] = v;
}
// fused split-K reduce + residual add + (optional) LayerNorm. Rows = BB, width DH.
__global__ void reduce_ln_kernel(float* __restrict__ h, const float* __restrict__ part,
                                 const float* __restrict__ b2, const float* __restrict__ lns,
                                 const float* __restrict__ lnb, float* __restrict__ z, int S) {
    int wid = threadIdx.x >> 5, lane = threadIdx.x & 31;
    int row = blockIdx.x * (blockDim.x >> 5) + wid;
    if (row >= BB) return;
    float4 r[4];
    const float4* hr = (const float4*)(h + (size_t)row * DH);
#pragma unroll
    for (int t = 0; t < 4; ++t) {
        int col4 = lane + 32 * t;
        float4 v = hr[col4];
        int colb = col4 * 4;
        float s0 = b2[colb], s1 = b2[colb + 1], s2 = b2[colb + 2], s3 = b2[colb + 3];
        for (int zz = 0; zz < S; ++zz) {
            const float4 p = *(const float4*)(part + (size_t)zz * BB * DH + (size_t)row * DH + colb);
            s0 += p.x; s1 += p.y; s2 += p.z; s3 += p.w;
        }
        v.x += s0; v.y += s1; v.z += s2; v.w += s3;
        r[t] = v;
    }
    float4* hw = (float4*)(h + (size_t)row * DH);
#pragma unroll
    for (int t = 0; t < 4; ++t) hw[lane + 32 * t] = r[t];
    if (!lns) return;
    float sum = 0.f;
#pragma unroll
    for (int t = 0; t < 4; ++t) sum += r[t].x + r[t].y + r[t].z + r[t].w;
    for (int o = 16; o > 0; o >>= 1) sum += __shfl_xor_sync(0xffffffffu, sum, o);
    float mu = sum / (float)DH;
    float vs = 0.f;
#pragma unroll
    for (int t = 0; t < 4; ++t) {
        float dx = r[t].x - mu, dy = r[t].y - mu, dz = r[t].z - mu, dw = r[t].w - mu;
        vs += dx * dx + dy * dy + dz * dz + dw * dw;
    }
    for (int o = 16; o > 0; o >>= 1) vs += __shfl_xor_sync(0xffffffffu, vs, o);
    float w = rsqrtf(vs / (float)DH + LN_EPS);
    float4* zr = (float4*)(z + (size_t)row * DH);
#pragma unroll
    for (int t = 0; t < 4; ++t) {
        int col = (lane + 32 * t) * 4;
        float4 o4;
        o4.x = (r[t].x - mu) * w * lns[col + 0] + lnb[col + 0];
        o4.y = (r[t].y - mu) * w * lns[col + 1] + lnb[col + 1];
        o4.z = (r[t].z - mu) * w * lns[col + 2] + lnb[col + 2];
        o4.w = (r[t].w - mu) * w * lns[col + 3] + lnb[col + 3];
        zr[lane + 32 * t] = o4;
    }
}

// ---------------- GEMM: cp.async 3-stage pipeline, 128x64 tile, BK=16, 128 thr, f32x2 ----
enum { EPI_NONE = 0, EPI_BIAS = 1, EPI_RELU_RES = 2 };

__global__ void __launch_bounds__(128) gemmp_kernel(
    const float* __restrict__ A, const float* __restrict__ B,
    const float* __restrict__ bias, const float* __restrict__ res,
    float* __restrict__ C, const int* __restrict__ rowsA, const int* __restrict__ rowsC,
    const int* __restrict__ cntp, const int* __restrict__ oovIdx, const float* __restrict__ oovEmb,
    int M, int Nb, int Nout, int K, int kChunk, int epi)
{
    __shared__ __align__(16) float As[3][128][16];
    __shared__ __align__(16) float Bs[3][16][64];
    int Meff = cntp ? *cntp : M;
    int t = threadIdx.x;
    int m0 = blockIdx.y * 128;
    if (m0 >= Meff) return;
    int n0 = blockIdx.x * 64;
    int ks = blockIdx.z * kChunk;
    int ke = ks + kChunk; if (ke > K) ke = K;
    int nkb = (ke - ks) >> 4;

    uint32_t sA = smem_u32(As);
    uint32_t sB = smem_u32(Bs);

    int mj0 = t >> 2, cA = t & 3;
    const float* aSrc[4];
    uint32_t aDst[4];
#pragma unroll
    for (int j = 0; j < 4; ++j) {
        int ml = 32 * j + mj0;
        int lm = m0 + ml;
        int gm;
        if (rowsA) gm = rowsA[lm < Meff ? lm : 0];
        else       gm = (lm < M) ? lm : 0;
        aSrc[j] = A + (size_t)gm * K + ks + 4 * cA;
        int cs = cA ^ ((ml >> 3) & 3);
        aDst[j] = sA + (uint32_t)(ml * 64 + cs * 16);
    }
    const float* bSrc[2];
    uint32_t bDst[2];
#pragma unroll
    for (int j = 0; j < 2; ++j) {
        int id = t + 128 * j;
        int kr = id >> 4, cb = id & 15;
        bSrc[j] = B + (size_t)(ks + kr) * Nb + n0 + 4 * cb;
        bDst[j] = sB + (uint32_t)(kr * 256 + cb * 16);
    }

    unsigned long long acc[8][4];
#pragma unroll
    for (int i = 0; i < 8; ++i)
#pragma unroll
        for (int j = 0; j < 4; ++j) acc[i][j] = 0ull;

    int gtw = (t >> 3) & 3;
    int ty8 = (t >> 3) * 8, tx8 = (t & 7) * 8;
    int fo[4];
#pragma unroll
    for (int c = 0; c < 4; ++c) fo[c] = 4 * (c ^ gtw);

    {
#pragma unroll
        for (int j = 0; j < 4; ++j) CP_ASYNC16(aDst[j], aSrc[j]);
#pragma unroll
        for (int j = 0; j < 2; ++j) CP_ASYNC16(bDst[j], bSrc[j]);
        CP_COMMIT();
        if (nkb > 1) {
#pragma unroll
            for (int j = 0; j < 4; ++j) CP_ASYNC16(aDst[j] + 8192u, aSrc[j] + 16);
#pragma unroll
            for (int j = 0; j < 2; ++j) CP_ASYNC16(bDst[j] + 4096u, bSrc[j] + (size_t)16 * Nb);
            CP_COMMIT();
        }
    }

    for (int i = 0; i < nkb; ++i) {
        if (i + 1 < nkb) { CP_WAIT1(); } else { CP_WAIT0(); }
        __syncthreads();
        int nx = i + 2;
        if (nx < nkb) {
            int st = nx % 3;
            uint32_t so = (uint32_t)st * 8192u, sob = (uint32_t)st * 4096u;
            int kof = nx << 4;
#pragma unroll
            for (int j = 0; j < 4; ++j) CP_ASYNC16(aDst[j] + so, aSrc[j] + kof);
#pragma unroll
            for (int j = 0; j < 2; ++j) CP_ASYNC16(bDst[j] + sob, bSrc[j] + (size_t)kof * Nb);
            CP_COMMIT();
        }
        int s = i % 3;
        const float (*Asr)[16] = As[s];
        const float (*Bsr)[64] = Bs[s];
#pragma unroll
        for (int kk = 0; kk < 16; ++kk) {
            int fs = fo[kk >> 2] + (kk & 3);
            unsigned long long ad[8], bd[4];
#pragma unroll
            for (int i8 = 0; i8 < 8; ++i8) {
                float av = Asr[ty8 + i8][fs];
                ad[i8] = pack2(av, av);
            }
#pragma unroll
            for (int j = 0; j < 4; ++j)
                bd[j] = *(const unsigned long long*)&Bsr[kk][tx8 + 2 * j];
#pragma unroll
            for (int i8 = 0; i8 < 8; ++i8)
#pragma unroll
                for (int j = 0; j < 4; ++j)
                    ffma2(acc[i8][j], ad[i8], bd[j]);
        }
    }

    float* Cz = C + (size_t)blockIdx.z * M * Nout;
    bool nfull = (n0 + 64 <= Nout);
#pragma unroll
    for (int i8 = 0; i8 < 8; ++i8) {
        int lm = m0 + ty8 + i8;
        if (lm >= Meff) continue;
        int gr = rowsC ? rowsC[lm] : lm;
        float v[8];
#pragma unroll
        for (int j = 0; j < 4; ++j) {
            v[2 * j]     = lo2(acc[i8][j]);
            v[2 * j + 1] = hi2(acc[i8][j]);
        }
        int gn0 = n0 + tx8;
        if (epi == EPI_RELU_RES) {
#pragma unroll
            for (int j = 0; j < 8; ++j) {
                float bi = bias[gn0 + j];
                float rv = res[(size_t)gr * Nout + gn0 + j];
                v[j] = fmaxf(v[j] + bi, 0.f) + rv;
            }
        } else if (epi == EPI_BIAS) {
#pragma unroll
            for (int j = 0; j < 8; ++j) v[j] += bias[gn0 + j];
        }
        if (oovIdx && oovIdx[lm] < 0) {
#pragma unroll
            for (int j = 0; j < 8; ++j) v[j] = oovEmb[gn0 + j];
        }
        float* crow = Cz + (size_t)gr * Nout;
        if (nfull) {
            *(float4*)(crow + gn0)     = make_float4(v[0], v[1], v[2], v[3]);
            *(float4*)(crow + gn0 + 4) = make_float4(v[4], v[5], v[6], v[7]);
        } else {
#pragma unroll
            for (int j = 0; j < 8; ++j)
                if (gn0 + j < Nout) crow[gn0 + j] = v[j];
        }
    }
}

// ---------------- launch ----------------
extern "C" void kernel_launch(void* const* d_in, const int* in_sizes, int n_in,
                              void* d_out, int out_size) {
    const int*   node_indices = (const int*)d_in[0];
    const int*   edge_index   = (const int*)d_in[1];
    const float* edge_weight  = (const float*)d_in[2];
    const float* partial_emb  = (const float*)d_in[3];
    const float* oov_emb      = (const float*)d_in[4];
    const float* gnn_ln_s     = (const float*)d_in[5];
    const float* gnn_ln_b     = (const float*)d_in[6];
    const float* gnn_w        = (const float*)d_in[7];
    const float* gnn_b        = (const float*)d_in[8];
    const float* post_w       = (const float*)d_in[9];
    const float* post_b       = (const float*)d_in[10];
    const float* pin_w        = (const float*)d_in[11];
    const float* pin_b        = (const float*)d_in[12];
    const float* blk_ln_s     = (const float*)d_in[13];
    const float* blk_ln_b     = (const float*)d_in[14];
    const float* blk_w1       = (const float*)d_in[15];
    const float* blk_b1       = (const float*)d_in[16];
    const float* blk_w2       = (const float*)d_in[17];
    const float* blk_b2       = (const float*)d_in[18];
    const float* pout_w       = (const float*)d_in[19];
    const float* pout_b       = (const float*)d_in[20];
    const float* gene         = (const float*)d_in[21];
    float*       out          = (float*)d_out;

    static float *p_x = nullptr, *p_hln, *p_agg, *p_bw, *p_pert, *p_h, *p_z, *p_t, *p_part, *p_proj, *p_geneT;
    static int   *p_deg, *p_off, *p_cur, *p_bsrc;
    static int   *p_flag2, *p_flag3, *p_list2, *p_list3, *p_cnt2, *p_bsum, *p_bpre;
    static cudaStream_t sB = nullptr, sC = nullptr;
    static cudaEvent_t  e0, e1, eCSR, eGene;
    if (!p_x) {
        cudaGetSymbolAddress((void**)&p_x,    g_x);
        cudaGetSymbolAddress((void**)&p_hln,  g_hln);
        cudaGetSymbolAddress((void**)&p_agg,  g_agg);
        cudaGetSymbolAddress((void**)&p_bw,   g_bw);
        cudaGetSymbolAddress((void**)&p_pert, g_pert);
        cudaGetSymbolAddress((void**)&p_h,    g_h);
        cudaGetSymbolAddress((void**)&p_z,    g_z);
        cudaGetSymbolAddress((void**)&p_t,    g_t);
        cudaGetSymbolAddress((void**)&p_part, g_part);
        cudaGetSymbolAddress((void**)&p_proj, g_proj);
        cudaGetSymbolAddress((void**)&p_geneT, g_geneT);
        cudaGetSymbolAddress((void**)&p_deg,  g_deg);
        cudaGetSymbolAddress((void**)&p_off,  g_off);
        cudaGetSymbolAddress((void**)&p_cur,  g_cur);
        cudaGetSymbolAddress((void**)&p_bsrc, g_bsrc);
        cudaGetSymbolAddress((void**)&p_flag2, g_flag2);
        cudaGetSymbolAddress((void**)&p_flag3, g_flag3);
        cudaGetSymbolAddress((void**)&p_list2, g_list2);
        cudaGetSymbolAddress((void**)&p_list3, g_list3);
        cudaGetSymbolAddress((void**)&p_cnt2,  g_cnt2);
        cudaGetSymbolAddress((void**)&p_bsum,  g_bsum);
        cudaGetSymbolAddress((void**)&p_bpre,  g_bpre);
        cudaStreamCreateWithFlags(&sB, cudaStreamNonBlocking);
        cudaStreamCreateWithFlags(&sC, cudaStreamNonBlocking);
        cudaEventCreateWithFlags(&e0,    cudaEventDisableTiming);
        cudaEventCreateWithFlags(&e1,    cudaEventDisableTiming);
        cudaEventCreateWithFlags(&eCSR,  cudaEventDisableTiming);
        cudaEventCreateWithFlags(&eGene, cudaEventDisableTiming);
    }

    const int NB = (NNODE + 255) / 256;
    const int LNG = (NNODE + 7) / 8;

    cudaEventRecord(e0, 0);

    // side C: gene transpose
    cudaStreamWaitEvent(sC, e0, 0);
    tgene_kernel<<<dim3(NGENE_PAD / 32, RNK / 32), dim3(32, 8), 0, sC>>>(gene, p_geneT);
    cudaEventRecord(eGene, sC);

    // main: init + seed, then fork CSR build to side B
    init_kernel<<<NB, 256>>>(p_deg, p_flag2, p_flag3, p_cnt2);
    flag_seed_kernel<<<1, BB>>>(node_indices, p_flag2, p_flag3, p_list3);
    cudaEventRecord(e1, 0);

    cudaStreamWaitEvent(sB, e1, 0);
    histflag_kernel<<<(EDGES + 255) / 256, 256, 0, sB>>>(edge_index, p_deg, p_flag3, p_flag2);
    scan1_kernel<<<NB, 256, 0, sB>>>(p_deg, p_off, p_bsum);
    scan2_kernel<<<1, 128, 0, sB>>>(p_bsum, p_bpre, NB);
    scan3_kernel<<<NB, 256, 0, sB>>>(p_deg, p_off, p_bpre, p_cur);
    scatter_kernel<<<(EDGES + 255) / 256, 256, 0, sB>>>(edge_index, edge_weight, p_cur, p_bsrc, p_bw);
    compact_kernel<<<NB, 256, 0, sB>>>(p_flag2, p_list2, p_cnt2);
    cudaEventRecord(eCSR, sB);

    // main (concurrent with CSR): LN layer 0 directly from partial_emb
    ln_kernel<<<LNG, 256>>>(partial_emb, gnn_ln_s, gnn_ln_b, p_hln, NNODE, DG, nullptr);

    cudaStreamWaitEvent(0, eCSR, 0);

    // ---- GNN layer 0: dense (residual = partial_emb) ----
    agg_kernel<<<(NNODE + 7) / 8, 256>>>(p_hln, p_agg, p_off, p_bsrc, p_bw, nullptr);
    gemmp_kernel<<<dim3(DG / 64, (NNODE + 127) / 128, 1), 128>>>(
        p_agg, gnn_w, gnn_b, partial_emb, p_x, nullptr, nullptr, nullptr, nullptr, nullptr,
        NNODE, DG, DG, DG, DG, EPI_RELU_RES);

    // ---- GNN layer 1: frontier F2 ----
    ln_kernel<<<LNG, 256>>>(p_x, gnn_ln_s + DG, gnn_ln_b + DG, p_hln, NNODE, DG, nullptr);
    agg_kernel<<<(NNODE + 7) / 8, 256>>>(p_hln, p_agg, p_off, p_bsrc, p_bw, p_flag2);
    gemmp_kernel<<<dim3(DG / 64, (NNODE + 127) / 128, 1), 128>>>(
        p_agg, gnn_w + (size_t)1 * DG * DG, gnn_b + DG, p_x, p_x, p_list2, p_list2, p_cnt2,
        nullptr, nullptr, NNODE, DG, DG, DG, DG, EPI_RELU_RES);

    // ---- GNN layer 2: frontier F3 (LN restricted to F2) ----
    ln_kernel<<<LNG, 256>>>(p_x, gnn_ln_s + 2 * DG, gnn_ln_b + 2 * DG, p_hln, NNODE, DG, p_flag2);
    agg_kernel<<<(NNODE + 7) / 8, 256>>>(p_hln, p_agg, p_off, p_bsrc, p_bw, p_flag3);
    gemmp_kernel<<<dim3(DG / 64, BB / 128, 1), 128>>>(
        p_agg, gnn_w + (size_t)2 * DG * DG, gnn_b + 2 * DG, p_x, p_x, p_list3, p_list3, nullptr,
        nullptr, nullptr, BB, DG, DG, DG, DG, EPI_RELU_RES);

    // ---- post_mp: gather via list3, oov replacement fused in epilogue ----
    gemmp_kernel<<<dim3(DG / 64, BB / 128, 1), 128>>>(
        p_x, post_w, post_b, nullptr, p_pert, p_list3, nullptr, nullptr,
        node_indices, oov_emb, BB, DG, DG, DG, DG, EPI_BIAS);

    // ---- proj_in ----
    gemmp_kernel<<<dim3(DH / 64, BB / 128, 1), 128>>>(
        p_pert, pin_w, pin_b, nullptr, p_h, nullptr, nullptr, nullptr, nullptr, nullptr,
        BB, DH, DH, DG, DG, EPI_BIAS);

    // ---- 6 residual MLP blocks (R11-proven split-K config) ----
    ln_kernel<<<BB / 8, 256>>>(p_h, blk_ln_s, blk_ln_b, p_z, BB, DH, nullptr);
    for (int i = 0; i < 6; ++i) {
        gemmp_kernel<<<dim3(DI / 64, BB / 128, 4), 128>>>(
            p_z, blk_w1 + (size_t)i * DH * DI, nullptr, nullptr, p_part,
            nullptr, nullptr, nullptr, nullptr, nullptr, BB, DI, DI, DH, DH / 4, EPI_NONE);
        reduce4_kernel<<<(BB * DI / 4 + 255) / 256, 256>>>(
            (float4*)p_t, (const float4*)p_part, (const float4*)(blk_b1 + i * DI),
            4, BB * DI / 4, DI / 4, 2);
        gemmp_kernel<<<dim3(DH / 64, BB / 128, 8), 128>>>(
            p_t, blk_w2 + (size_t)i * DI * DH, nullptr, nullptr, p_part,
            nullptr, nullptr, nullptr, nullptr, nullptr, BB, DH, DH, DI, DI / 8, EPI_NONE);
        const float* lns = (i < 5) ? blk_ln_s + (i + 1) * DH : nullptr;
        const float* lnb = (i < 5) ? blk_ln_b + (i + 1) * DH : nullptr;
        reduce_ln_kernel<<<BB / 8, 256>>>(p_h, p_part, blk_b2 + i * DH, lns, lnb, p_z, 8);
    }

    // ---- proj_out (split-K x2) ----
    gemmp_kernel<<<dim3((NCLS * RNK) / 64, BB / 128, 2), 128>>>(
        p_h, pout_w, nullptr, nullptr, p_part, nullptr, nullptr, nullptr, nullptr, nullptr,
        BB, NCLS * RNK, NCLS * RNK, DH, DH / 2, EPI_NONE);
    reduce4_kernel<<<(BB * NCLS * RNK / 4 + 255) / 256, 256>>>(
        (float4*)p_proj, (const float4*)p_part, (const float4*)pout_b,
        2, BB * NCLS * RNK / 4, NCLS * RNK / 4, 0);

    // ---- logits (wait for geneT) ----
    cudaStreamWaitEvent(0, eGene, 0);
    gemmp_kernel<<<dim3(NGENE_PAD / 64, (BB * NCLS) / 128, 1), 128>>>(
        p_proj, p_geneT, nullptr, nullptr, out, nullptr, nullptr, nullptr, nullptr, nullptr,
        BB * NCLS, NGENE_PAD, NGENE, RNK, RNK, EPI_NONE);
}

// round 16
// speedup vs baseline: 1.0609x; 1.0563x over previous
#include <cuda_runtime.h>
#include <math.h>
#include <stdint.h>

// ---------------- problem constants ----------------
#define NNODE   20000
#define NPAD    20096
#define EDGES   640000
#define BB      256
#define DG      256
#define DH      512
#define DI      2048
#define RNK     512
#define NCLS    3
#define NGENE   6640
#define NGENE_PAD 6656
#define LN_EPS  1e-5f

// ---------------- scratch (device globals) ----------------
__device__ float g_x   [NPAD * DG];
__device__ float g_hln [NPAD * DG];
__device__ float g_agg [NPAD * DG];
__device__ int   g_deg [NNODE];
__device__ int   g_off [NNODE + 1];
__device__ int   g_cur [NNODE];
__device__ int   g_bsrc[EDGES];
__device__ float g_bw  [EDGES];
__device__ float g_pert[BB * DG];
__device__ float g_h   [BB * DH];
__device__ float g_z   [BB * DH];
__device__ float g_t   [BB * DI];
__device__ float g_part[4 * BB * DI];
__device__ float g_proj[BB * NCLS * RNK];
__device__ float g_geneT[RNK * NGENE_PAD];
__device__ int   g_flag2[NNODE];
__device__ int   g_flag3[NNODE];
__device__ int   g_list2[NNODE];
__device__ int   g_list3[BB];
__device__ int   g_cnt2[1];
__device__ int   g_bsum[128];
__device__ int   g_bpre[128];

// ---------------- packed f32x2 + cp.async helpers ----------------
__device__ __forceinline__ void ffma2(unsigned long long &d, unsigned long long a, unsigned long long b) {
    asm("fma.rn.f32x2 %0, %1, %2, %0;" : "+l"(d) : "l"(a), "l"(b));
}
__device__ __forceinline__ unsigned long long pack2(float x, float y) {
    unsigned long long r;
    asm("mov.b64 %0, {%1, %2};" : "=l"(r) : "f"(x), "f"(y));
    return r;
}
__device__ __forceinline__ float lo2(unsigned long long v) {
    return __uint_as_float((unsigned)(v & 0xffffffffull));
}
__device__ __forceinline__ float hi2(unsigned long long v) {
    return __uint_as_float((unsigned)(v >> 32));
}
__device__ __forceinline__ uint32_t smem_u32(const void* p) {
    uint32_t a;
    asm("{ .reg .u64 t; cvta.to.shared.u64 t, %1; cvt.u32.u64 %0, t; }" : "=r"(a) : "l"(p));
    return a;
}
#define CP_ASYNC16(dst, src) \
    asm volatile("cp.async.cg.shared.global [%0], [%1], 16;" :: "r"(dst), "l"(src))
#define CP_COMMIT() asm volatile("cp.async.commit_group;" ::: "memory")
#define CP_WAIT1()  asm volatile("cp.async.wait_group 1;" ::: "memory")
#define CP_WAIT0()  asm volatile("cp.async.wait_group 0;" ::: "memory")

// ---------------- preprocessing kernels ----------------
__global__ void init_kernel(int* deg, int* flag2, int* flag3, int* cnt2) {
    int i = blockIdx.x * blockDim.x + threadIdx.x;
    if (i < NNODE) { deg[i] = 0; flag2[i] = 0; flag3[i] = 0; }
    if (i == 0) cnt2[0] = 0;
}
__global__ void flag_seed_kernel(const int* __restrict__ idx, int* flag2, int* flag3, int* list3) {
    int i = threadIdx.x;
    int id = idx[i];
    int safe = id < 0 ? 0 : id;
    flag3[safe] = 1;
    flag2[safe] = 1;
    list3[i] = safe;
}
__global__ void histflag_kernel(const int* __restrict__ ei, int* __restrict__ deg,
                                const int* __restrict__ flag3, int* __restrict__ flag2) {
    int e = blockIdx.x * blockDim.x + threadIdx.x;
    if (e < EDGES) {
        int d = ei[EDGES + e];
        atomicAdd(&deg[d], 1);
        if (flag3[d]) flag2[ei[e]] = 1;
    }
}
__global__ void scan1_kernel(const int* __restrict__ deg, int* __restrict__ off, int* __restrict__ bsum) {
    __shared__ int sh[256];
    int tid = threadIdx.x, i = blockIdx.x * 256 + tid;
    int v = (i < NNODE) ? deg[i] : 0;
    sh[tid] = v;
    __syncthreads();
    for (int o = 1; o < 256; o <<= 1) {
        int u = (tid >= o) ? sh[tid - o] : 0;
        __syncthreads();
        sh[tid] += u;
        __syncthreads();
    }
    if (i < NNODE) off[i + 1] = sh[tid];
    if (tid == 255) bsum[blockIdx.x] = sh[255];
}
__global__ void scan2_kernel(const int* __restrict__ bsum, int* __restrict__ bpre, int nb) {
    __shared__ int sh[128];
    int tid = threadIdx.x;
    int v = (tid < nb) ? bsum[tid] : 0;
    sh[tid] = v;
    __syncthreads();
    for (int o = 1; o < 128; o <<= 1) {
        int u = (tid >= o) ? sh[tid - o] : 0;
        __syncthreads();
        sh[tid] += u;
        __syncthreads();
    }
    if (tid < nb) bpre[tid] = sh[tid] - v;
}
__global__ void scan3_kernel(const int* __restrict__ deg, int* __restrict__ off,
                             const int* __restrict__ bpre, int* __restrict__ cur) {
    int i = blockIdx.x * blockDim.x + threadIdx.x;
    if (i < NNODE) {
        int o = off[i + 1] + bpre[i >> 8];
        off[i + 1] = o;
        cur[i] = o - deg[i];
        if (i == 0) off[0] = 0;
    }
}
__global__ void scatter_kernel(const int* __restrict__ ei, const float* __restrict__ ew,
                               int* __restrict__ cur, int* __restrict__ bsrc, float* __restrict__ bw) {
    int i = blockIdx.x * blockDim.x + threadIdx.x;
    if (i < EDGES) {
        int d = ei[EDGES + i];
        int p = atomicAdd(&cur[d], 1);
        bsrc[p] = ei[i];
        bw[p]   = ew[i];
    }
}
__global__ void compact_kernel(const int* __restrict__ flag2, int* __restrict__ list2,
                               int* __restrict__ cnt2) {
    int i = blockIdx.x * blockDim.x + threadIdx.x;
    if (i < NNODE && flag2[i]) {
        int p = atomicAdd(cnt2, 1);
        list2[p] = i;
    }
}
__global__ void tgene_kernel(const float* __restrict__ g, float* __restrict__ gt) {
    __shared__ float tb[32][33];
    int n0 = blockIdx.x * 32, r0 = blockIdx.y * 32;
    int tx = threadIdx.x, ty = threadIdx.y;
    for (int dy = 0; dy < 32; dy += 8) {
        int n = n0 + ty + dy;
        tb[ty + dy][tx] = (n < NGENE) ? g[(size_t)n * RNK + r0 + tx] : 0.f;
    }
    __syncthreads();
    for (int dy = 0; dy < 32; dy += 8)
        gt[(size_t)(r0 + ty + dy) * NGENE_PAD + n0 + tx] = tb[tx][ty + dy];
}

// ---------------- LN / agg / misc ----------------
__global__ void ln_kernel(const float* __restrict__ x, const float* __restrict__ s,
                          const float* __restrict__ b, float* __restrict__ y,
                          int rows, int D, const int* __restrict__ flag) {
    int wid = threadIdx.x >> 5, lane = threadIdx.x & 31;
    int row = blockIdx.x * (blockDim.x >> 5) + wid;
    if (row >= rows) return;
    if (flag && !flag[row]) return;
    const float4* xr = (const float4*)(x + (size_t)row * D);
    int nf = D >> 7;
    float4 r[4];
    float sum = 0.f;
    for (int t = 0; t < nf; ++t) {
        r[t] = xr[lane + 32 * t];
        sum += r[t].x + r[t].y + r[t].z + r[t].w;
    }
    for (int o = 16; o > 0; o >>= 1) sum += __shfl_xor_sync(0xffffffffu, sum, o);
    float mu = sum / (float)D;
    float vs = 0.f;
    for (int t = 0; t < nf; ++t) {
        float dx = r[t].x - mu, dy = r[t].y - mu, dz = r[t].z - mu, dw = r[t].w - mu;
        vs += dx * dx + dy * dy + dz * dz + dw * dw;
    }
    for (int o = 16; o > 0; o >>= 1) vs += __shfl_xor_sync(0xffffffffu, vs, o);
    float w = rsqrtf(vs / (float)D + LN_EPS);
    float4* yr = (float4*)(y + (size_t)row * D);
    for (int t = 0; t < nf; ++t) {
        int col = (lane + 32 * t) * 4;
        float4 o4;
        o4.x = (r[t].x - mu) * w * s[col + 0] + b[col + 0];
        o4.y = (r[t].y - mu) * w * s[col + 1] + b[col + 1];
        o4.z = (r[t].z - mu) * w * s[col + 2] + b[col + 2];
        o4.w = (r[t].w - mu) * w * s[col + 3] + b[col + 3];
        yr[lane + 32 * t] = o4;
    }
}
__global__ void agg_kernel(const float* __restrict__ hln, float* __restrict__ agg,
                           const int* __restrict__ off, const int* __restrict__ bsrc,
                           const float* __restrict__ bw, const int* __restrict__ flag) {
    int wid = threadIdx.x >> 5, lane = threadIdx.x & 31;
    int node = blockIdx.x * (blockDim.x >> 5) + wid;
    if (node >= NNODE) return;
    if (flag && !flag[node]) return;
    int st = off[node], en = off[node + 1];
    float4 a0 = make_float4(0, 0, 0, 0), a1 = make_float4(0, 0, 0, 0);
    for (int j = st; j < en; ++j) {
        int s = bsrc[j];
        float w = bw[j];
        const float4* r = (const float4*)(hln + s * DG);
        float4 v0 = r[lane], v1 = r[lane + 32];
        a0.x = fmaf(w, v0.x, a0.x); a0.y = fmaf(w, v0.y, a0.y);
        a0.z = fmaf(w, v0.z, a0.z); a0.w = fmaf(w, v0.w, a0.w);
        a1.x = fmaf(w, v1.x, a1.x); a1.y = fmaf(w, v1.y, a1.y);
        a1.z = fmaf(w, v1.z, a1.z); a1.w = fmaf(w, v1.w, a1.w);
    }
    float4* o = (float4*)(agg + node * DG);
    o[lane] = a0;
    o[lane + 32] = a1;
}
// vectorized split-K reduce. mode 0: dst = b + sum ; 2: dst = gelu(b + sum)
__global__ void reduce4_kernel(float4* __restrict__ dst, const float4* __restrict__ part,
                               const float4* __restrict__ bias, int S, int total4, int N4, int mode) {
    int i = blockIdx.x * blockDim.x + threadIdx.x;
    if (i >= total4) return;
    float4 v = bias[i % N4];
    for (int z = 0; z < S; ++z) {
        float4 p = part[(size_t)z * total4 + i];
        v.x += p.x; v.y += p.y; v.z += p.z; v.w += p.w;
    }
    if (mode == 2) {
        v.x = 0.5f * v.x * (1.f + erff(v.x * 0.70710678118654752f));
        v.y = 0.5f * v.y * (1.f + erff(v.y * 0.70710678118654752f));
        v.z = 0.5f * v.z * (1.f + erff(v.z * 0.70710678118654752f));
        v.w = 0.5f * v.w * (1.f + erff(v.w * 0.70710678118654752f));
    }
    dst[i] = v;
}
// split-K reduce + oov override: pert[row] = oov ? oov_emb : bias + sum. [BB x DG]
__global__ void reduce_post_kernel(float* __restrict__ pert, const float* __restrict__ part,
                                   const float* __restrict__ bias, const int* __restrict__ idx,
                                   const float* __restrict__ oovEmb, int S) {
    int row = blockIdx.x, c4 = threadIdx.x;   // 64 threads = DG/4
    int colb = c4 * 4;
    bool oov = idx[row] < 0;
    float4 v;
    if (oov) {
        v = *(const float4*)(oovEmb + colb);
    } else {
        v = *(const float4*)(bias + colb);
        for (int z = 0; z < S; ++z) {
            const float4 p = *(const float4*)(part + ((size_t)z * BB + row) * DG + colb);
            v.x += p.x; v.y += p.y; v.z += p.z; v.w += p.w;
        }
    }
    *(float4*)(pert + (size_t)row * DG + colb) = v;
}
// split-K reduce + relu + residual, scattered via rows: x[rows[r]] = relu(b+sum) + x[rows[r]]. [BB x DG]
__global__ void reduce_gnn2_kernel(float* __restrict__ x, const float* __restrict__ part,
                                   const float* __restrict__ bias, const int* __restrict__ rows, int S) {
    int r = blockIdx.x, c4 = threadIdx.x;     // 64 threads
    int colb = c4 * 4;
    int gr = rows[r];
    float4 v = *(const float4*)(bias + colb);
    for (int z = 0; z < S; ++z) {
        const float4 p = *(const float4*)(part + ((size_t)z * BB + r) * DG + colb);
        v.x += p.x; v.y += p.y; v.z += p.z; v.w += p.w;
    }
    float4 rv = *(const float4*)(x + (size_t)gr * DG + colb);
    v.x = fmaxf(v.x, 0.f) + rv.x;
    v.y = fmaxf(v.y, 0.f) + rv.y;
    v.z = fmaxf(v.z, 0.f) + rv.z;
    v.w = fmaxf(v.w, 0.f) + rv.w;
    *(float4*)(x + (size_t)gr * DG + colb) = v;
}
// fused split-K reduce + residual add + (optional) LayerNorm. Rows = BB, width DH.
__global__ void reduce_ln_kernel(float* __restrict__ h, const float* __restrict__ part,
                                 const float* __restrict__ b2, const float* __restrict__ lns,
                                 const float* __restrict__ lnb, float* __restrict__ z, int S) {
    int wid = threadIdx.x >> 5, lane = threadIdx.x & 31;
    int row = blockIdx.x * (blockDim.x >> 5) + wid;
    if (row >= BB) return;
    float4 r[4];
    const float4* hr = (const float4*)(h + (size_t)row * DH);
#pragma unroll
    for (int t = 0; t < 4; ++t) {
        int col4 = lane + 32 * t;
        float4 v = hr[col4];
        int colb = col4 * 4;
        float s0 = b2[colb], s1 = b2[colb + 1], s2 = b2[colb + 2], s3 = b2[colb + 3];
        for (int zz = 0; zz < S; ++zz) {
            const float4 p = *(const float4*)(part + (size_t)zz * BB * DH + (size_t)row * DH + colb);
            s0 += p.x; s1 += p.y; s2 += p.z; s3 += p.w;
        }
        v.x += s0; v.y += s1; v.z += s2; v.w += s3;
        r[t] = v;
    }
    float4* hw = (float4*)(h + (size_t)row * DH);
#pragma unroll
    for (int t = 0; t < 4; ++t) hw[lane + 32 * t] = r[t];
    if (!lns) return;
    float sum = 0.f;
#pragma unroll
    for (int t = 0; t < 4; ++t) sum += r[t].x + r[t].y + r[t].z + r[t].w;
    for (int o = 16; o > 0; o >>= 1) sum += __shfl_xor_sync(0xffffffffu, sum, o);
    float mu = sum / (float)DH;
    float vs = 0.f;
#pragma unroll
    for (int t = 0; t < 4; ++t) {
        float dx = r[t].x - mu, dy = r[t].y - mu, dz = r[t].z - mu, dw = r[t].w - mu;
        vs += dx * dx + dy * dy + dz * dz + dw * dw;
    }
    for (int o = 16; o > 0; o >>= 1) vs += __shfl_xor_sync(0xffffffffu, vs, o);
    float w = rsqrtf(vs / (float)DH + LN_EPS);
    float4* zr = (float4*)(z + (size_t)row * DH);
#pragma unroll
    for (int t = 0; t < 4; ++t) {
        int col = (lane + 32 * t) * 4;
        float4 o4;
        o4.x = (r[t].x - mu) * w * lns[col + 0] + lnb[col + 0];
        o4.y = (r[t].y - mu) * w * lns[col + 1] + lnb[col + 1];
        o4.z = (r[t].z - mu) * w * lns[col + 2] + lnb[col + 2];
        o4.w = (r[t].w - mu) * w * lns[col + 3] + lnb[col + 3];
        zr[lane + 32 * t] = o4;
    }
}

// ---------------- GEMM: cp.async 3-stage pipeline, 128x64 tile, BK=16, 128 thr, f32x2 ----
enum { EPI_NONE = 0, EPI_BIAS = 1, EPI_RELU_RES = 2 };

__global__ void __launch_bounds__(128) gemmp_kernel(
    const float* __restrict__ A, const float* __restrict__ B,
    const float* __restrict__ bias, const float* __restrict__ res,
    float* __restrict__ C, const int* __restrict__ rowsA, const int* __restrict__ rowsC,
    const int* __restrict__ cntp, int M, int Nb, int Nout, int K, int kChunk, int epi)
{
    __shared__ __align__(16) float As[3][128][16];
    __shared__ __align__(16) float Bs[3][16][64];
    int Meff = cntp ? *cntp : M;
    int t = threadIdx.x;
    int m0 = blockIdx.y * 128;
    if (m0 >= Meff) return;
    int n0 = blockIdx.x * 64;
    int ks = blockIdx.z * kChunk;
    int ke = ks + kChunk; if (ke > K) ke = K;
    int nkb = (ke - ks) >> 4;

    uint32_t sA = smem_u32(As);
    uint32_t sB = smem_u32(Bs);

    int mj0 = t >> 2, cA = t & 3;
    const float* aSrc[4];
    uint32_t aDst[4];
#pragma unroll
    for (int j = 0; j < 4; ++j) {
        int ml = 32 * j + mj0;
        int lm = m0 + ml;
        int gm;
        if (rowsA) gm = rowsA[lm < Meff ? lm : 0];
        else       gm = (lm < M) ? lm : 0;
        aSrc[j] = A + (size_t)gm * K + ks + 4 * cA;
        int cs = cA ^ ((ml >> 3) & 3);
        aDst[j] = sA + (uint32_t)(ml * 64 + cs * 16);
    }
    const float* bSrc[2];
    uint32_t bDst[2];
#pragma unroll
    for (int j = 0; j < 2; ++j) {
        int id = t + 128 * j;
        int kr = id >> 4, cb = id & 15;
        bSrc[j] = B + (size_t)(ks + kr) * Nb + n0 + 4 * cb;
        bDst[j] = sB + (uint32_t)(kr * 256 + cb * 16);
    }

    unsigned long long acc[8][4];
#pragma unroll
    for (int i = 0; i < 8; ++i)
#pragma unroll
        for (int j = 0; j < 4; ++j) acc[i][j] = 0ull;

    int gtw = (t >> 3) & 3;
    int ty8 = (t >> 3) * 8, tx8 = (t & 7) * 8;
    int fo[4];
#pragma unroll
    for (int c = 0; c < 4; ++c) fo[c] = 4 * (c ^ gtw);

    {
#pragma unroll
        for (int j = 0; j < 4; ++j) CP_ASYNC16(aDst[j], aSrc[j]);
#pragma unroll
        for (int j = 0; j < 2; ++j) CP_ASYNC16(bDst[j], bSrc[j]);
        CP_COMMIT();
        if (nkb > 1) {
#pragma unroll
            for (int j = 0; j < 4; ++j) CP_ASYNC16(aDst[j] + 8192u, aSrc[j] + 16);
#pragma unroll
            for (int j = 0; j < 2; ++j) CP_ASYNC16(bDst[j] + 4096u, bSrc[j] + (size_t)16 * Nb);
            CP_COMMIT();
        }
    }

    for (int i = 0; i < nkb; ++i) {
        if (i + 1 < nkb) { CP_WAIT1(); } else { CP_WAIT0(); }
        __syncthreads();
        int nx = i + 2;
        if (nx < nkb) {
            int st = nx % 3;
            uint32_t so = (uint32_t)st * 8192u, sob = (uint32_t)st * 4096u;
            int kof = nx << 4;
#pragma unroll
            for (int j = 0; j < 4; ++j) CP_ASYNC16(aDst[j] + so, aSrc[j] + kof);
#pragma unroll
            for (int j = 0; j < 2; ++j) CP_ASYNC16(bDst[j] + sob, bSrc[j] + (size_t)kof * Nb);
            CP_COMMIT();
        }
        int s = i % 3;
        const float (*Asr)[16] = As[s];
        const float (*Bsr)[64] = Bs[s];
#pragma unroll
        for (int kk = 0; kk < 16; ++kk) {
            int fs = fo[kk >> 2] + (kk & 3);
            unsigned long long ad[8], bd[4];
#pragma unroll
            for (int i8 = 0; i8 < 8; ++i8) {
                float av = Asr[ty8 + i8][fs];
                ad[i8] = pack2(av, av);
            }
#pragma unroll
            for (int j = 0; j < 4; ++j)
                bd[j] = *(const unsigned long long*)&Bsr[kk][tx8 + 2 * j];
#pragma unroll
            for (int i8 = 0; i8 < 8; ++i8)
#pragma unroll
                for (int j = 0; j < 4; ++j)
                    ffma2(acc[i8][j], ad[i8], bd[j]);
        }
    }

    float* Cz = C + (size_t)blockIdx.z * M * Nout;
    bool nfull = (n0 + 64 <= Nout);
#pragma unroll
    for (int i8 = 0; i8 < 8; ++i8) {
        int lm = m0 + ty8 + i8;
        if (lm >= Meff) continue;
        int gr = rowsC ? rowsC[lm] : lm;
        float v[8];
#pragma unroll
        for (int j = 0; j < 4; ++j) {
            v[2 * j]     = lo2(acc[i8][j]);
            v[2 * j + 1] = hi2(acc[i8][j]);
        }
        int gn0 = n0 + tx8;
        if (epi == EPI_RELU_RES) {
#pragma unroll
            for (int j = 0; j < 8; ++j) {
                float bi = bias[gn0 + j];
                float rv = res[(size_t)gr * Nout + gn0 + j];
                v[j] = fmaxf(v[j] + bi, 0.f) + rv;
            }
        } else if (epi == EPI_BIAS) {
#pragma unroll
            for (int j = 0; j < 8; ++j) v[j] += bias[gn0 + j];
        }
        float* crow = Cz + (size_t)gr * Nout;
        if (nfull) {
            *(float4*)(crow + gn0)     = make_float4(v[0], v[1], v[2], v[3]);
            *(float4*)(crow + gn0 + 4) = make_float4(v[4], v[5], v[6], v[7]);
        } else {
#pragma unroll
            for (int j = 0; j < 8; ++j)
                if (gn0 + j < Nout) crow[gn0 + j] = v[j];
        }
    }
}

// ---------------- launch ----------------
extern "C" void kernel_launch(void* const* d_in, const int* in_sizes, int n_in,
                              void* d_out, int out_size) {
    const int*   node_indices = (const int*)d_in[0];
    const int*   edge_index   = (const int*)d_in[1];
    const float* edge_weight  = (const float*)d_in[2];
    const float* partial_emb  = (const float*)d_in[3];
    const float* oov_emb      = (const float*)d_in[4];
    const float* gnn_ln_s     = (const float*)d_in[5];
    const float* gnn_ln_b     = (const float*)d_in[6];
    const float* gnn_w        = (const float*)d_in[7];
    const float* gnn_b        = (const float*)d_in[8];
    const float* post_w       = (const float*)d_in[9];
    const float* post_b       = (const float*)d_in[10];
    const float* pin_w        = (const float*)d_in[11];
    const float* pin_b        = (const float*)d_in[12];
    const float* blk_ln_s     = (const float*)d_in[13];
    const float* blk_ln_b     = (const float*)d_in[14];
    const float* blk_w1       = (const float*)d_in[15];
    const float* blk_b1       = (const float*)d_in[16];
    const float* blk_w2       = (const float*)d_in[17];
    const float* blk_b2       = (const float*)d_in[18];
    const float* pout_w       = (const float*)d_in[19];
    const float* pout_b       = (const float*)d_in[20];
    const float* gene         = (const float*)d_in[21];
    float*       out          = (float*)d_out;

    static float *p_x = nullptr, *p_hln, *p_agg, *p_bw, *p_pert, *p_h, *p_z, *p_t, *p_part, *p_proj, *p_geneT;
    static int   *p_deg, *p_off, *p_cur, *p_bsrc;
    static int   *p_flag2, *p_flag3, *p_list2, *p_list3, *p_cnt2, *p_bsum, *p_bpre;
    static cudaStream_t sB = nullptr, sC = nullptr;
    static cudaEvent_t  e0, e1, eCSR, eGene;
    if (!p_x) {
        cudaGetSymbolAddress((void**)&p_x,    g_x);
        cudaGetSymbolAddress((void**)&p_hln,  g_hln);
        cudaGetSymbolAddress((void**)&p_agg,  g_agg);
        cudaGetSymbolAddress((void**)&p_bw,   g_bw);
        cudaGetSymbolAddress((void**)&p_pert, g_pert);
        cudaGetSymbolAddress((void**)&p_h,    g_h);
        cudaGetSymbolAddress((void**)&p_z,    g_z);
        cudaGetSymbolAddress((void**)&p_t,    g_t);
        cudaGetSymbolAddress((void**)&p_part, g_part);
        cudaGetSymbolAddress((void**)&p_proj, g_proj);
        cudaGetSymbolAddress((void**)&p_geneT, g_geneT);
        cudaGetSymbolAddress((void**)&p_deg,  g_deg);
        cudaGetSymbolAddress((void**)&p_off,  g_off);
        cudaGetSymbolAddress((void**)&p_cur,  g_cur);
        cudaGetSymbolAddress((void**)&p_bsrc, g_bsrc);
        cudaGetSymbolAddress((void**)&p_flag2, g_flag2);
        cudaGetSymbolAddress((void**)&p_flag3, g_flag3);
        cudaGetSymbolAddress((void**)&p_list2, g_list2);
        cudaGetSymbolAddress((void**)&p_list3, g_list3);
        cudaGetSymbolAddress((void**)&p_cnt2,  g_cnt2);
        cudaGetSymbolAddress((void**)&p_bsum,  g_bsum);
        cudaGetSymbolAddress((void**)&p_bpre,  g_bpre);
        cudaStreamCreateWithFlags(&sB, cudaStreamNonBlocking);
        cudaStreamCreateWithFlags(&sC, cudaStreamNonBlocking);
        cudaEventCreateWithFlags(&e0,    cudaEventDisableTiming);
        cudaEventCreateWithFlags(&e1,    cudaEventDisableTiming);
        cudaEventCreateWithFlags(&eCSR,  cudaEventDisableTiming);
        cudaEventCreateWithFlags(&eGene, cudaEventDisableTiming);
    }

    const int NB = (NNODE + 255) / 256;
    const int LNG = (NNODE + 7) / 8;

    cudaEventRecord(e0, 0);

    // side C: gene transpose
    cudaStreamWaitEvent(sC, e0, 0);
    tgene_kernel<<<dim3(NGENE_PAD / 32, RNK / 32), dim3(32, 8), 0, sC>>>(gene, p_geneT);
    cudaEventRecord(eGene, sC);

    // main: init + seed, then fork CSR build to side B
    init_kernel<<<NB, 256>>>(p_deg, p_flag2, p_flag3, p_cnt2);
    flag_seed_kernel<<<1, BB>>>(node_indices, p_flag2, p_flag3, p_list3);
    cudaEventRecord(e1, 0);

    cudaStreamWaitEvent(sB, e1, 0);
    histflag_kernel<<<(EDGES + 255) / 256, 256, 0, sB>>>(edge_index, p_deg, p_flag3, p_flag2);
    scan1_kernel<<<NB, 256, 0, sB>>>(p_deg, p_off, p_bsum);
    scan2_kernel<<<1, 128, 0, sB>>>(p_bsum, p_bpre, NB);
    scan3_kernel<<<NB, 256, 0, sB>>>(p_deg, p_off, p_bpre, p_cur);
    scatter_kernel<<<(EDGES + 255) / 256, 256, 0, sB>>>(edge_index, edge_weight, p_cur, p_bsrc, p_bw);
    compact_kernel<<<NB, 256, 0, sB>>>(p_flag2, p_list2, p_cnt2);
    cudaEventRecord(eCSR, sB);

    // main (concurrent with CSR): LN layer 0 directly from partial_emb
    ln_kernel<<<LNG, 256>>>(partial_emb, gnn_ln_s, gnn_ln_b, p_hln, NNODE, DG, nullptr);

    cudaStreamWaitEvent(0, eCSR, 0);

    // ---- GNN layer 0: dense (residual = partial_emb) ----
    agg_kernel<<<(NNODE + 7) / 8, 256>>>(p_hln, p_agg, p_off, p_bsrc, p_bw, nullptr);
    gemmp_kernel<<<dim3(DG / 64, (NNODE + 127) / 128, 1), 128>>>(
        p_agg, gnn_w, gnn_b, partial_emb, p_x, nullptr, nullptr, nullptr,
        NNODE, DG, DG, DG, DG, EPI_RELU_RES);

    // ---- GNN layer 1: frontier F2 ----
    ln_kernel<<<LNG, 256>>>(p_x, gnn_ln_s + DG, gnn_ln_b + DG, p_hln, NNODE, DG, nullptr);
    agg_kernel<<<(NNODE + 7) / 8, 256>>>(p_hln, p_agg, p_off, p_bsrc, p_bw, p_flag2);
    gemmp_kernel<<<dim3(DG / 64, (NNODE + 127) / 128, 1), 128>>>(
        p_agg, gnn_w + (size_t)1 * DG * DG, gnn_b + DG, p_x, p_x, p_list2, p_list2, p_cnt2,
        NNODE, DG, DG, DG, DG, EPI_RELU_RES);

    // ---- GNN layer 2: frontier F3 — split-K x4 (32 blocks), epilogue in reduce ----
    ln_kernel<<<LNG, 256>>>(p_x, gnn_ln_s + 2 * DG, gnn_ln_b + 2 * DG, p_hln, NNODE, DG, p_flag2);
    agg_kernel<<<(NNODE + 7) / 8, 256>>>(p_hln, p_agg, p_off, p_bsrc, p_bw, p_flag3);
    gemmp_kernel<<<dim3(DG / 64, BB / 128, 4), 128>>>(
        p_agg, gnn_w + (size_t)2 * DG * DG, nullptr, nullptr, p_part, p_list3, nullptr, nullptr,
        BB, DG, DG, DG, DG / 4, EPI_NONE);
    reduce_gnn2_kernel<<<BB, DG / 4>>>(p_x, p_part, gnn_b + 2 * DG, p_list3, 4);

    // ---- post_mp: split-K x4, oov+bias in reduce ----
    gemmp_kernel<<<dim3(DG / 64, BB / 128, 4), 128>>>(
        p_x, post_w, nullptr, nullptr, p_part, p_list3, nullptr, nullptr,
        BB, DG, DG, DG, DG / 4, EPI_NONE);
    reduce_post_kernel<<<BB, DG / 4>>>(p_pert, p_part, post_b, node_indices, oov_emb, 4);

    // ---- proj_in: split-K x4 (64 blocks) ----
    gemmp_kernel<<<dim3(DH / 64, BB / 128, 4), 128>>>(
        p_pert, pin_w, nullptr, nullptr, p_part, nullptr, nullptr, nullptr,
        BB, DH, DH, DG, DG / 4, EPI_NONE);
    reduce4_kernel<<<(BB * DH / 4 + 255) / 256, 256>>>(
        (float4*)p_h, (const float4*)p_part, (const float4*)pin_b, 4, BB * DH / 4, DH / 4, 0);

    // ---- 6 residual MLP blocks (R11-proven split-K config) ----
    ln_kernel<<<BB / 8, 256>>>(p_h, blk_ln_s, blk_ln_b, p_z, BB, DH, nullptr);
    for (int i = 0; i < 6; ++i) {
        gemmp_kernel<<<dim3(DI / 64, BB / 128, 4), 128>>>(
            p_z, blk_w1 + (size_t)i * DH * DI, nullptr, nullptr, p_part,
            nullptr, nullptr, nullptr, BB, DI, DI, DH, DH / 4, EPI_NONE);
        reduce4_kernel<<<(BB * DI / 4 + 255) / 256, 256>>>(
            (float4*)p_t, (const float4*)p_part, (const float4*)(blk_b1 + i * DI),
            4, BB * DI / 4, DI / 4, 2);
        gemmp_kernel<<<dim3(DH / 64, BB / 128, 8), 128>>>(
            p_t, blk_w2 + (size_t)i * DI * DH, nullptr, nullptr, p_part,
            nullptr, nullptr, nullptr, BB, DH, DH, DI, DI / 8, EPI_NONE);
        const float* lns = (i < 5) ? blk_ln_s + (i + 1) * DH : nullptr;
        const float* lnb = (i < 5) ? blk_ln_b + (i + 1) * DH : nullptr;
        reduce_ln_kernel<<<BB / 8, 256>>>(p_h, p_part, blk_b2 + i * DH, lns, lnb, p_z, 8);
    }

    // ---- proj_out (split-K x2) ----
    gemmp_kernel<<<dim3((NCLS * RNK) / 64, BB / 128, 2), 128>>>(
        p_h, pout_w, nullptr, nullptr, p_part, nullptr, nullptr, nullptr,
        BB, NCLS * RNK, NCLS * RNK, DH, DH / 2, EPI_NONE);
    reduce4_kernel<<<(BB * NCLS * RNK / 4 + 255) / 256, 256>>>(
        (float4*)p_proj, (const float4*)p_part, (const float4*)pout_b,
        2, BB * NCLS * RNK / 4, NCLS * RNK / 4, 0);

    // ---- logits (wait for geneT) ----
    cudaStreamWaitEvent(0, eGene, 0);
    gemmp_kernel<<<dim3(NGENE_PAD / 64, (BB * NCLS) / 128, 1), 128>>>(
        p_proj, p_geneT, nullptr, nullptr, out, nullptr, nullptr, nullptr,
        BB * NCLS, NGENE_PAD, NGENE, RNK, RNK, EPI_NONE);
}

// round 17
// speedup vs baseline: 1.0640x; 1.0029x over previous
#include <cuda_runtime.h>
#include <math.h>
#include <stdint.h>

// ---------------- problem constants ----------------
#define NNODE   20000
#define NPAD    20096
#define EDGES   640000
#define BB      256
#define DG      256
#define DH      512
#define DI      2048
#define RNK     512
#define NCLS    3
#define NGENE   6640
#define NGENE_PAD 6656
#define LN_EPS  1e-5f

// ---------------- scratch (device globals) ----------------
__device__ float g_x   [NPAD * DG];
__device__ float g_hln [NPAD * DG];
__device__ float g_agg [NPAD * DG];
__device__ int   g_deg [NNODE];
__device__ int   g_off [NNODE + 1];
__device__ int   g_cur [NNODE];
__device__ int   g_bsrc[EDGES];
__device__ float g_bw  [EDGES];
__device__ float g_pert[BB * DG];
__device__ float g_h   [BB * DH];
__device__ float g_z   [BB * DH];
__device__ float g_t   [BB * DI];
__device__ float g_part[4 * BB * DI];
__device__ float g_proj[BB * NCLS * RNK];
__device__ float g_geneT[RNK * NGENE_PAD];
__device__ int   g_flag2[NNODE];
__device__ int   g_flag3[NNODE];
__device__ int   g_list2[NNODE];
__device__ int   g_list3[BB];
__device__ int   g_cnt2[1];
__device__ int   g_bsum[128];
__device__ int   g_bpre[128];

// ---------------- packed f32x2 + cp.async helpers ----------------
__device__ __forceinline__ void ffma2(unsigned long long &d, unsigned long long a, unsigned long long b) {
    asm("fma.rn.f32x2 %0, %1, %2, %0;" : "+l"(d) : "l"(a), "l"(b));
}
__device__ __forceinline__ unsigned long long pack2(float x, float y) {
    unsigned long long r;
    asm("mov.b64 %0, {%1, %2};" : "=l"(r) : "f"(x), "f"(y));
    return r;
}
__device__ __forceinline__ float lo2(unsigned long long v) {
    return __uint_as_float((unsigned)(v & 0xffffffffull));
}
__device__ __forceinline__ float hi2(unsigned long long v) {
    return __uint_as_float((unsigned)(v >> 32));
}
__device__ __forceinline__ uint32_t smem_u32(const void* p) {
    uint32_t a;
    asm("{ .reg .u64 t; cvta.to.shared.u64 t, %1; cvt.u32.u64 %0, t; }" : "=r"(a) : "l"(p));
    return a;
}
#define CP_ASYNC16(dst, src) \
    asm volatile("cp.async.cg.shared.global [%0], [%1], 16;" :: "r"(dst), "l"(src))
#define CP_COMMIT() asm volatile("cp.async.commit_group;" ::: "memory")
#define CP_WAIT1()  asm volatile("cp.async.wait_group 1;" ::: "memory")
#define CP_WAIT0()  asm volatile("cp.async.wait_group 0;" ::: "memory")

// ---------------- preprocessing kernels ----------------
__global__ void init_kernel(int* deg, int* flag2, int* flag3, int* cnt2) {
    int i = blockIdx.x * blockDim.x + threadIdx.x;
    if (i < NNODE) { deg[i] = 0; flag2[i] = 0; flag3[i] = 0; }
    if (i == 0) cnt2[0] = 0;
}
__global__ void flag_seed_kernel(const int* __restrict__ idx, int* flag2, int* flag3, int* list3) {
    int i = threadIdx.x;
    int id = idx[i];
    int safe = id < 0 ? 0 : id;
    flag3[safe] = 1;
    flag2[safe] = 1;
    list3[i] = safe;
}
__global__ void histflag_kernel(const int* __restrict__ ei, int* __restrict__ deg,
                                const int* __restrict__ flag3, int* __restrict__ flag2) {
    int e = blockIdx.x * blockDim.x + threadIdx.x;
    if (e < EDGES) {
        int d = ei[EDGES + e];
        atomicAdd(&deg[d], 1);
        if (flag3[d]) flag2[ei[e]] = 1;
    }
}
__global__ void scan1_kernel(const int* __restrict__ deg, int* __restrict__ off, int* __restrict__ bsum) {
    __shared__ int sh[256];
    int tid = threadIdx.x, i = blockIdx.x * 256 + tid;
    int v = (i < NNODE) ? deg[i] : 0;
    sh[tid] = v;
    __syncthreads();
    for (int o = 1; o < 256; o <<= 1) {
        int u = (tid >= o) ? sh[tid - o] : 0;
        __syncthreads();
        sh[tid] += u;
        __syncthreads();
    }
    if (i < NNODE) off[i + 1] = sh[tid];
    if (tid == 255) bsum[blockIdx.x] = sh[255];
}
__global__ void scan2_kernel(const int* __restrict__ bsum, int* __restrict__ bpre, int nb) {
    __shared__ int sh[128];
    int tid = threadIdx.x;
    int v = (tid < nb) ? bsum[tid] : 0;
    sh[tid] = v;
    __syncthreads();
    for (int o = 1; o < 128; o <<= 1) {
        int u = (tid >= o) ? sh[tid - o] : 0;
        __syncthreads();
        sh[tid] += u;
        __syncthreads();
    }
    if (tid < nb) bpre[tid] = sh[tid] - v;
}
__global__ void scan3_kernel(const int* __restrict__ deg, int* __restrict__ off,
                             const int* __restrict__ bpre, int* __restrict__ cur) {
    int i = blockIdx.x * blockDim.x + threadIdx.x;
    if (i < NNODE) {
        int o = off[i + 1] + bpre[i >> 8];
        off[i + 1] = o;
        cur[i] = o - deg[i];
        if (i == 0) off[0] = 0;
    }
}
__global__ void scatter_kernel(const int* __restrict__ ei, const float* __restrict__ ew,
                               int* __restrict__ cur, int* __restrict__ bsrc, float* __restrict__ bw) {
    int i = blockIdx.x * blockDim.x + threadIdx.x;
    if (i < EDGES) {
        int d = ei[EDGES + i];
        int p = atomicAdd(&cur[d], 1);
        bsrc[p] = ei[i];
        bw[p]   = ew[i];
    }
}
__global__ void compact_kernel(const int* __restrict__ flag2, int* __restrict__ list2,
                               int* __restrict__ cnt2) {
    int i = blockIdx.x * blockDim.x + threadIdx.x;
    if (i < NNODE && flag2[i]) {
        int p = atomicAdd(cnt2, 1);
        list2[p] = i;
    }
}
__global__ void tgene_kernel(const float* __restrict__ g, float* __restrict__ gt) {
    __shared__ float tb[32][33];
    int n0 = blockIdx.x * 32, r0 = blockIdx.y * 32;
    int tx = threadIdx.x, ty = threadIdx.y;
    for (int dy = 0; dy < 32; dy += 8) {
        int n = n0 + ty + dy;
        tb[ty + dy][tx] = (n < NGENE) ? g[(size_t)n * RNK + r0 + tx] : 0.f;
    }
    __syncthreads();
    for (int dy = 0; dy < 32; dy += 8)
        gt[(size_t)(r0 + ty + dy) * NGENE_PAD + n0 + tx] = tb[tx][ty + dy];
}

// ---------------- LN / agg / misc ----------------
__global__ void ln_kernel(const float* __restrict__ x, const float* __restrict__ s,
                          const float* __restrict__ b, float* __restrict__ y,
                          int rows, int D, const int* __restrict__ flag) {
    int wid = threadIdx.x >> 5, lane = threadIdx.x & 31;
    int row = blockIdx.x * (blockDim.x >> 5) + wid;
    if (row >= rows) return;
    if (flag && !flag[row]) return;
    const float4* xr = (const float4*)(x + (size_t)row * D);
    int nf = D >> 7;
    float4 r[4];
    float sum = 0.f;
    for (int t = 0; t < nf; ++t) {
        r[t] = xr[lane + 32 * t];
        sum += r[t].x + r[t].y + r[t].z + r[t].w;
    }
    for (int o = 16; o > 0; o >>= 1) sum += __shfl_xor_sync(0xffffffffu, sum, o);
    float mu = sum / (float)D;
    float vs = 0.f;
    for (int t = 0; t < nf; ++t) {
        float dx = r[t].x - mu, dy = r[t].y - mu, dz = r[t].z - mu, dw = r[t].w - mu;
        vs += dx * dx + dy * dy + dz * dz + dw * dw;
    }
    for (int o = 16; o > 0; o >>= 1) vs += __shfl_xor_sync(0xffffffffu, vs, o);
    float w = rsqrtf(vs / (float)D + LN_EPS);
    float4* yr = (float4*)(y + (size_t)row * D);
    for (int t = 0; t < nf; ++t) {
        int col = (lane + 32 * t) * 4;
        float4 o4;
        o4.x = (r[t].x - mu) * w * s[col + 0] + b[col + 0];
        o4.y = (r[t].y - mu) * w * s[col + 1] + b[col + 1];
        o4.z = (r[t].z - mu) * w * s[col + 2] + b[col + 2];
        o4.w = (r[t].w - mu) * w * s[col + 3] + b[col + 3];
        yr[lane + 32 * t] = o4;
    }
}
__global__ void agg_kernel(const float* __restrict__ hln, float* __restrict__ agg,
                           const int* __restrict__ off, const int* __restrict__ bsrc,
                           const float* __restrict__ bw, const int* __restrict__ flag) {
    int wid = threadIdx.x >> 5, lane = threadIdx.x & 31;
    int node = blockIdx.x * (blockDim.x >> 5) + wid;
    if (node >= NNODE) return;
    if (flag && !flag[node]) return;
    int st = off[node], en = off[node + 1];
    float4 a0 = make_float4(0, 0, 0, 0), a1 = make_float4(0, 0, 0, 0);
    for (int j = st; j < en; ++j) {
        int s = bsrc[j];
        float w = bw[j];
        const float4* r = (const float4*)(hln + s * DG);
        float4 v0 = r[lane], v1 = r[lane + 32];
        a0.x = fmaf(w, v0.x, a0.x); a0.y = fmaf(w, v0.y, a0.y);
        a0.z = fmaf(w, v0.z, a0.z); a0.w = fmaf(w, v0.w, a0.w);
        a1.x = fmaf(w, v1.x, a1.x); a1.y = fmaf(w, v1.y, a1.y);
        a1.z = fmaf(w, v1.z, a1.z); a1.w = fmaf(w, v1.w, a1.w);
    }
    float4* o = (float4*)(agg + node * DG);
    o[lane] = a0;
    o[lane + 32] = a1;
}
// vectorized split-K reduce. mode 0: dst = b + sum ; 2: dst = gelu(b + sum)
__global__ void reduce4_kernel(float4* __restrict__ dst, const float4* __restrict__ part,
                               const float4* __restrict__ bias, int S, int total4, int N4, int mode) {
    int i = blockIdx.x * blockDim.x + threadIdx.x;
    if (i >= total4) return;
    float4 v = bias[i % N4];
    for (int z = 0; z < S; ++z) {
        float4 p = part[(size_t)z * total4 + i];
        v.x += p.x; v.y += p.y; v.z += p.z; v.w += p.w;
    }
    if (mode == 2) {
        v.x = 0.5f * v.x * (1.f + erff(v.x * 0.70710678118654752f));
        v.y = 0.5f * v.y * (1.f + erff(v.y * 0.70710678118654752f));
        v.z = 0.5f * v.z * (1.f + erff(v.z * 0.70710678118654752f));
        v.w = 0.5f * v.w * (1.f + erff(v.w * 0.70710678118654752f));
    }
    dst[i] = v;
}
// split-K reduce + oov override: pert[row] = oov ? oov_emb : bias + sum. [BB x DG]
__global__ void reduce_post_kernel(float* __restrict__ pert, const float* __restrict__ part,
                                   const float* __restrict__ bias, const int* __restrict__ idx,
                                   const float* __restrict__ oovEmb, int S) {
    int row = blockIdx.x, c4 = threadIdx.x;   // 64 threads = DG/4
    int colb = c4 * 4;
    bool oov = idx[row] < 0;
    float4 v;
    if (oov) {
        v = *(const float4*)(oovEmb + colb);
    } else {
        v = *(const float4*)(bias + colb);
        for (int z = 0; z < S; ++z) {
            const float4 p = *(const float4*)(part + ((size_t)z * BB + row) * DG + colb);
            v.x += p.x; v.y += p.y; v.z += p.z; v.w += p.w;
        }
    }
    *(float4*)(pert + (size_t)row * DG + colb) = v;
}
// split-K reduce + relu + residual, scattered via rows: x[rows[r]] = relu(b+sum) + x[rows[r]]. [BB x DG]
__global__ void reduce_gnn2_kernel(float* __restrict__ x, const float* __restrict__ part,
                                   const float* __restrict__ bias, const int* __restrict__ rows, int S) {
    int r = blockIdx.x, c4 = threadIdx.x;     // 64 threads
    int colb = c4 * 4;
    int gr = rows[r];
    float4 v = *(const float4*)(bias + colb);
    for (int z = 0; z < S; ++z) {
        const float4 p = *(const float4*)(part + ((size_t)z * BB + r) * DG + colb);
        v.x += p.x; v.y += p.y; v.z += p.z; v.w += p.w;
    }
    float4 rv = *(const float4*)(x + (size_t)gr * DG + colb);
    v.x = fmaxf(v.x, 0.f) + rv.x;
    v.y = fmaxf(v.y, 0.f) + rv.y;
    v.z = fmaxf(v.z, 0.f) + rv.z;
    v.w = fmaxf(v.w, 0.f) + rv.w;
    *(float4*)(x + (size_t)gr * DG + colb) = v;
}
// fused split-K reduce + residual add + (optional) LayerNorm. Rows = BB, width DH.
__global__ void reduce_ln_kernel(float* __restrict__ h, const float* __restrict__ part,
                                 const float* __restrict__ b2, const float* __restrict__ lns,
                                 const float* __restrict__ lnb, float* __restrict__ z, int S) {
    int wid = threadIdx.x >> 5, lane = threadIdx.x & 31;
    int row = blockIdx.x * (blockDim.x >> 5) + wid;
    if (row >= BB) return;
    float4 r[4];
    const float4* hr = (const float4*)(h + (size_t)row * DH);
#pragma unroll
    for (int t = 0; t < 4; ++t) {
        int col4 = lane + 32 * t;
        float4 v = hr[col4];
        int colb = col4 * 4;
        float s0 = b2[colb], s1 = b2[colb + 1], s2 = b2[colb + 2], s3 = b2[colb + 3];
        for (int zz = 0; zz < S; ++zz) {
            const float4 p = *(const float4*)(part + (size_t)zz * BB * DH + (size_t)row * DH + colb);
            s0 += p.x; s1 += p.y; s2 += p.z; s3 += p.w;
        }
        v.x += s0; v.y += s1; v.z += s2; v.w += s3;
        r[t] = v;
    }
    float4* hw = (float4*)(h + (size_t)row * DH);
#pragma unroll
    for (int t = 0; t < 4; ++t) hw[lane + 32 * t] = r[t];
    if (!lns) return;
    float sum = 0.f;
#pragma unroll
    for (int t = 0; t < 4; ++t) sum += r[t].x + r[t].y + r[t].z + r[t].w;
    for (int o = 16; o > 0; o >>= 1) sum += __shfl_xor_sync(0xffffffffu, sum, o);
    float mu = sum / (float)DH;
    float vs = 0.f;
#pragma unroll
    for (int t = 0; t < 4; ++t) {
        float dx = r[t].x - mu, dy = r[t].y - mu, dz = r[t].z - mu, dw = r[t].w - mu;
        vs += dx * dx + dy * dy + dz * dz + dw * dw;
    }
    for (int o = 16; o > 0; o >>= 1) vs += __shfl_xor_sync(0xffffffffu, vs, o);
    float w = rsqrtf(vs / (float)DH + LN_EPS);
    float4* zr = (float4*)(z + (size_t)row * DH);
#pragma unroll
    for (int t = 0; t < 4; ++t) {
        int col = (lane + 32 * t) * 4;
        float4 o4;
        o4.x = (r[t].x - mu) * w * lns[col + 0] + lnb[col + 0];
        o4.y = (r[t].y - mu) * w * lns[col + 1] + lnb[col + 1];
        o4.z = (r[t].z - mu) * w * lns[col + 2] + lnb[col + 2];
        o4.w = (r[t].w - mu) * w * lns[col + 3] + lnb[col + 3];
        zr[lane + 32 * t] = o4;
    }
}

// ---------------- GEMM: cp.async 3-stage pipeline, 128x64 tile, BK=16, 128 thr, f32x2 ----
enum { EPI_NONE = 0, EPI_BIAS = 1, EPI_RELU_RES = 2 };

__global__ void __launch_bounds__(128) gemmp_kernel(
    const float* __restrict__ A, const float* __restrict__ B,
    const float* __restrict__ bias, const float* __restrict__ res,
    float* __restrict__ C, const int* __restrict__ rowsA, const int* __restrict__ rowsC,
    const int* __restrict__ cntp, int M, int Nb, int Nout, int K, int kChunk, int epi)
{
    __shared__ __align__(16) float As[3][128][16];
    __shared__ __align__(16) float Bs[3][16][64];
    int Meff = cntp ? *cntp : M;
    int t = threadIdx.x;
    int m0 = blockIdx.y * 128;
    if (m0 >= Meff) return;
    int n0 = blockIdx.x * 64;
    int ks = blockIdx.z * kChunk;
    int ke = ks + kChunk; if (ke > K) ke = K;
    int nkb = (ke - ks) >> 4;

    uint32_t sA = smem_u32(As);
    uint32_t sB = smem_u32(Bs);

    int mj0 = t >> 2, cA = t & 3;
    const float* aSrc[4];
    uint32_t aDst[4];
#pragma unroll
    for (int j = 0; j < 4; ++j) {
        int ml = 32 * j + mj0;
        int lm = m0 + ml;
        int gm;
        if (rowsA) gm = rowsA[lm < Meff ? lm : 0];
        else       gm = (lm < M) ? lm : 0;
        aSrc[j] = A + (size_t)gm * K + ks + 4 * cA;
        int cs = cA ^ ((ml >> 3) & 3);
        aDst[j] = sA + (uint32_t)(ml * 64 + cs * 16);
    }
    const float* bSrc[2];
    uint32_t bDst[2];
#pragma unroll
    for (int j = 0; j < 2; ++j) {
        int id = t + 128 * j;
        int kr = id >> 4, cb = id & 15;
        bSrc[j] = B + (size_t)(ks + kr) * Nb + n0 + 4 * cb;
        bDst[j] = sB + (uint32_t)(kr * 256 + cb * 16);
    }

    unsigned long long acc[8][4];
#pragma unroll
    for (int i = 0; i < 8; ++i)
#pragma unroll
        for (int j = 0; j < 4; ++j) acc[i][j] = 0ull;

    int gtw = (t >> 3) & 3;
    int ty8 = (t >> 3) * 8, tx8 = (t & 7) * 8;
    int fo[4];
#pragma unroll
    for (int c = 0; c < 4; ++c) fo[c] = 4 * (c ^ gtw);

    {
#pragma unroll
        for (int j = 0; j < 4; ++j) CP_ASYNC16(aDst[j], aSrc[j]);
#pragma unroll
        for (int j = 0; j < 2; ++j) CP_ASYNC16(bDst[j], bSrc[j]);
        CP_COMMIT();
        if (nkb > 1) {
#pragma unroll
            for (int j = 0; j < 4; ++j) CP_ASYNC16(aDst[j] + 8192u, aSrc[j] + 16);
#pragma unroll
            for (int j = 0; j < 2; ++j) CP_ASYNC16(bDst[j] + 4096u, bSrc[j] + (size_t)16 * Nb);
            CP_COMMIT();
        }
    }

    for (int i = 0; i < nkb; ++i) {
        if (i + 1 < nkb) { CP_WAIT1(); } else { CP_WAIT0(); }
        __syncthreads();
        int nx = i + 2;
        if (nx < nkb) {
            int st = nx % 3;
            uint32_t so = (uint32_t)st * 8192u, sob = (uint32_t)st * 4096u;
            int kof = nx << 4;
#pragma unroll
            for (int j = 0; j < 4; ++j) CP_ASYNC16(aDst[j] + so, aSrc[j] + kof);
#pragma unroll
            for (int j = 0; j < 2; ++j) CP_ASYNC16(bDst[j] + sob, bSrc[j] + (size_t)kof * Nb);
            CP_COMMIT();
        }
        int s = i % 3;
        const float (*Asr)[16] = As[s];
        const float (*Bsr)[64] = Bs[s];
#pragma unroll
        for (int kk = 0; kk < 16; ++kk) {
            int fs = fo[kk >> 2] + (kk & 3);
            unsigned long long ad[8], bd[4];
#pragma unroll
            for (int i8 = 0; i8 < 8; ++i8) {
                float av = Asr[ty8 + i8][fs];
                ad[i8] = pack2(av, av);
            }
#pragma unroll
            for (int j = 0; j < 4; ++j)
                bd[j] = *(const unsigned long long*)&Bsr[kk][tx8 + 2 * j];
#pragma unroll
            for (int i8 = 0; i8 < 8; ++i8)
#pragma unroll
                for (int j = 0; j < 4; ++j)
                    ffma2(acc[i8][j], ad[i8], bd[j]);
        }
    }

    float* Cz = C + (size_t)blockIdx.z * M * Nout;
    bool nfull = (n0 + 64 <= Nout);
#pragma unroll
    for (int i8 = 0; i8 < 8; ++i8) {
        int lm = m0 + ty8 + i8;
        if (lm >= Meff) continue;
        int gr = rowsC ? rowsC[lm] : lm;
        float v[8];
#pragma unroll
        for (int j = 0; j < 4; ++j) {
            v[2 * j]     = lo2(acc[i8][j]);
            v[2 * j + 1] = hi2(acc[i8][j]);
        }
        int gn0 = n0 + tx8;
        if (epi == EPI_RELU_RES) {
#pragma unroll
            for (int j = 0; j < 8; ++j) {
                float bi = bias[gn0 + j];
                float rv = res[(size_t)gr * Nout + gn0 + j];
                v[j] = fmaxf(v[j] + bi, 0.f) + rv;
            }
        } else if (epi == EPI_BIAS) {
#pragma unroll
            for (int j = 0; j < 8; ++j) v[j] += bias[gn0 + j];
        }
        float* crow = Cz + (size_t)gr * Nout;
        if (nfull) {
            *(float4*)(crow + gn0)     = make_float4(v[0], v[1], v[2], v[3]);
            *(float4*)(crow + gn0 + 4) = make_float4(v[4], v[5], v[6], v[7]);
        } else {
#pragma unroll
            for (int j = 0; j < 8; ++j)
                if (gn0 + j < Nout) crow[gn0 + j] = v[j];
        }
    }
}

// ---------------- launch ----------------
extern "C" void kernel_launch(void* const* d_in, const int* in_sizes, int n_in,
                              void* d_out, int out_size) {
    const int*   node_indices = (const int*)d_in[0];
    const int*   edge_index   = (const int*)d_in[1];
    const float* edge_weight  = (const float*)d_in[2];
    const float* partial_emb  = (const float*)d_in[3];
    const float* oov_emb      = (const float*)d_in[4];
    const float* gnn_ln_s     = (const float*)d_in[5];
    const float* gnn_ln_b     = (const float*)d_in[6];
    const float* gnn_w        = (const float*)d_in[7];
    const float* gnn_b        = (const float*)d_in[8];
    const float* post_w       = (const float*)d_in[9];
    const float* post_b       = (const float*)d_in[10];
    const float* pin_w        = (const float*)d_in[11];
    const float* pin_b        = (const float*)d_in[12];
    const float* blk_ln_s     = (const float*)d_in[13];
    const float* blk_ln_b     = (const float*)d_in[14];
    const float* blk_w1       = (const float*)d_in[15];
    const float* blk_b1       = (const float*)d_in[16];
    const float* blk_w2       = (const float*)d_in[17];
    const float* blk_b2       = (const float*)d_in[18];
    const float* pout_w       = (const float*)d_in[19];
    const float* pout_b       = (const float*)d_in[20];
    const float* gene         = (const float*)d_in[21];
    float*       out          = (float*)d_out;

    static float *p_x = nullptr, *p_hln, *p_agg, *p_bw, *p_pert, *p_h, *p_z, *p_t, *p_part, *p_proj, *p_geneT;
    static int   *p_deg, *p_off, *p_cur, *p_bsrc;
    static int   *p_flag2, *p_flag3, *p_list2, *p_list3, *p_cnt2, *p_bsum, *p_bpre;
    static cudaStream_t sB = nullptr, sC = nullptr;
    static cudaEvent_t  e0, e1, eCSR, eGene;
    if (!p_x) {
        cudaGetSymbolAddress((void**)&p_x,    g_x);
        cudaGetSymbolAddress((void**)&p_hln,  g_hln);
        cudaGetSymbolAddress((void**)&p_agg,  g_agg);
        cudaGetSymbolAddress((void**)&p_bw,   g_bw);
        cudaGetSymbolAddress((void**)&p_pert, g_pert);
        cudaGetSymbolAddress((void**)&p_h,    g_h);
        cudaGetSymbolAddress((void**)&p_z,    g_z);
        cudaGetSymbolAddress((void**)&p_t,    g_t);
        cudaGetSymbolAddress((void**)&p_part, g_part);
        cudaGetSymbolAddress((void**)&p_proj, g_proj);
        cudaGetSymbolAddress((void**)&p_geneT, g_geneT);
        cudaGetSymbolAddress((void**)&p_deg,  g_deg);
        cudaGetSymbolAddress((void**)&p_off,  g_off);
        cudaGetSymbolAddress((void**)&p_cur,  g_cur);
        cudaGetSymbolAddress((void**)&p_bsrc, g_bsrc);
        cudaGetSymbolAddress((void**)&p_flag2, g_flag2);
        cudaGetSymbolAddress((void**)&p_flag3, g_flag3);
        cudaGetSymbolAddress((void**)&p_list2, g_list2);
        cudaGetSymbolAddress((void**)&p_list3, g_list3);
        cudaGetSymbolAddress((void**)&p_cnt2,  g_cnt2);
        cudaGetSymbolAddress((void**)&p_bsum,  g_bsum);
        cudaGetSymbolAddress((void**)&p_bpre,  g_bpre);
        cudaStreamCreateWithFlags(&sB, cudaStreamNonBlocking);
        cudaStreamCreateWithFlags(&sC, cudaStreamNonBlocking);
        cudaEventCreateWithFlags(&e0,    cudaEventDisableTiming);
        cudaEventCreateWithFlags(&e1,    cudaEventDisableTiming);
        cudaEventCreateWithFlags(&eCSR,  cudaEventDisableTiming);
        cudaEventCreateWithFlags(&eGene, cudaEventDisableTiming);
    }

    const int NB = (NNODE + 255) / 256;
    const int LNG = (NNODE + 7) / 8;

    cudaEventRecord(e0, 0);

    // side C: gene transpose
    cudaStreamWaitEvent(sC, e0, 0);
    tgene_kernel<<<dim3(NGENE_PAD / 32, RNK / 32), dim3(32, 8), 0, sC>>>(gene, p_geneT);
    cudaEventRecord(eGene, sC);

    // main: init + seed, then fork CSR build to side B
    init_kernel<<<NB, 256>>>(p_deg, p_flag2, p_flag3, p_cnt2);
    flag_seed_kernel<<<1, BB>>>(node_indices, p_flag2, p_flag3, p_list3);
    cudaEventRecord(e1, 0);

    cudaStreamWaitEvent(sB, e1, 0);
    histflag_kernel<<<(EDGES + 255) / 256, 256, 0, sB>>>(edge_index, p_deg, p_flag3, p_flag2);
    scan1_kernel<<<NB, 256, 0, sB>>>(p_deg, p_off, p_bsum);
    scan2_kernel<<<1, 128, 0, sB>>>(p_bsum, p_bpre, NB);
    scan3_kernel<<<NB, 256, 0, sB>>>(p_deg, p_off, p_bpre, p_cur);
    scatter_kernel<<<(EDGES + 255) / 256, 256, 0, sB>>>(edge_index, edge_weight, p_cur, p_bsrc, p_bw);
    compact_kernel<<<NB, 256, 0, sB>>>(p_flag2, p_list2, p_cnt2);
    cudaEventRecord(eCSR, sB);

    // main (concurrent with CSR): LN layer 0 directly from partial_emb
    ln_kernel<<<LNG, 256>>>(partial_emb, gnn_ln_s, gnn_ln_b, p_hln, NNODE, DG, nullptr);

    cudaStreamWaitEvent(0, eCSR, 0);

    // ---- GNN layer 0: dense (residual = partial_emb) ----
    agg_kernel<<<(NNODE + 7) / 8, 256>>>(p_hln, p_agg, p_off, p_bsrc, p_bw, nullptr);
    gemmp_kernel<<<dim3(DG / 64, (NNODE + 127) / 128, 1), 128>>>(
        p_agg, gnn_w, gnn_b, partial_emb, p_x, nullptr, nullptr, nullptr,
        NNODE, DG, DG, DG, DG, EPI_RELU_RES);

    // ---- GNN layer 1: frontier F2 ----
    ln_kernel<<<LNG, 256>>>(p_x, gnn_ln_s + DG, gnn_ln_b + DG, p_hln, NNODE, DG, nullptr);
    agg_kernel<<<(NNODE + 7) / 8, 256>>>(p_hln, p_agg, p_off, p_bsrc, p_bw, p_flag2);
    gemmp_kernel<<<dim3(DG / 64, (NNODE + 127) / 128, 1), 128>>>(
        p_agg, gnn_w + (size_t)1 * DG * DG, gnn_b + DG, p_x, p_x, p_list2, p_list2, p_cnt2,
        NNODE, DG, DG, DG, DG, EPI_RELU_RES);

    // ---- GNN layer 2: frontier F3 — split-K x8 (64 blocks) ----
    ln_kernel<<<LNG, 256>>>(p_x, gnn_ln_s + 2 * DG, gnn_ln_b + 2 * DG, p_hln, NNODE, DG, p_flag2);
    agg_kernel<<<(NNODE + 7) / 8, 256>>>(p_hln, p_agg, p_off, p_bsrc, p_bw, p_flag3);
    gemmp_kernel<<<dim3(DG / 64, BB / 128, 8), 128>>>(
        p_agg, gnn_w + (size_t)2 * DG * DG, nullptr, nullptr, p_part, p_list3, nullptr, nullptr,
        BB, DG, DG, DG, DG / 8, EPI_NONE);
    reduce_gnn2_kernel<<<BB, DG / 4>>>(p_x, p_part, gnn_b + 2 * DG, p_list3, 8);

    // ---- post_mp: split-K x8, oov+bias in reduce ----
    gemmp_kernel<<<dim3(DG / 64, BB / 128, 8), 128>>>(
        p_x, post_w, nullptr, nullptr, p_part, p_list3, nullptr, nullptr,
        BB, DG, DG, DG, DG / 8, EPI_NONE);
    reduce_post_kernel<<<BB, DG / 4>>>(p_pert, p_part, post_b, node_indices, oov_emb, 8);

    // ---- proj_in: split-K x8 (128 blocks) ----
    gemmp_kernel<<<dim3(DH / 64, BB / 128, 8), 128>>>(
        p_pert, pin_w, nullptr, nullptr, p_part, nullptr, nullptr, nullptr,
        BB, DH, DH, DG, DG / 8, EPI_NONE);
    reduce4_kernel<<<(BB * DH / 4 + 255) / 256, 256>>>(
        (float4*)p_h, (const float4*)p_part, (const float4*)pin_b, 8, BB * DH / 4, DH / 4, 0);

    // ---- 6 residual MLP blocks (R11-proven split-K config) ----
    ln_kernel<<<BB / 8, 256>>>(p_h, blk_ln_s, blk_ln_b, p_z, BB, DH, nullptr);
    for (int i = 0; i < 6; ++i) {
        gemmp_kernel<<<dim3(DI / 64, BB / 128, 4), 128>>>(
            p_z, blk_w1 + (size_t)i * DH * DI, nullptr, nullptr, p_part,
            nullptr, nullptr, nullptr, BB, DI, DI, DH, DH / 4, EPI_NONE);
        reduce4_kernel<<<(BB * DI / 4 + 255) / 256, 256>>>(
            (float4*)p_t, (const float4*)p_part, (const float4*)(blk_b1 + i * DI),
            4, BB * DI / 4, DI / 4, 2);
        gemmp_kernel<<<dim3(DH / 64, BB / 128, 8), 128>>>(
            p_t, blk_w2 + (size_t)i * DI * DH, nullptr, nullptr, p_part,
            nullptr, nullptr, nullptr, BB, DH, DH, DI, DI / 8, EPI_NONE);
        const float* lns = (i < 5) ? blk_ln_s + (i + 1) * DH : nullptr;
        const float* lnb = (i < 5) ? blk_ln_b + (i + 1) * DH : nullptr;
        reduce_ln_kernel<<<BB / 8, 256>>>(p_h, p_part, blk_b2 + i * DH, lns, lnb, p_z, 8);
    }

    // ---- proj_out (split-K x4, isolated retry) ----
    gemmp_kernel<<<dim3((NCLS * RNK) / 64, BB / 128, 4), 128>>>(
        p_h, pout_w, nullptr, nullptr, p_part, nullptr, nullptr, nullptr,
        BB, NCLS * RNK, NCLS * RNK, DH, DH / 4, EPI_NONE);
    reduce4_kernel<<<(BB * NCLS * RNK / 4 + 255) / 256, 256>>>(
        (float4*)p_proj, (const float4*)p_part, (const float4*)pout_b,
        4, BB * NCLS * RNK / 4, NCLS * RNK / 4, 0);

    // ---- logits (wait for geneT) ----
    cudaStreamWaitEvent(0, eGene, 0);
    gemmp_kernel<<<dim3(NGENE_PAD / 64, (BB * NCLS) / 128, 1), 128>>>(
        p_proj, p_geneT, nullptr, nullptr, out, nullptr, nullptr, nullptr,
        BB * NCLS, NGENE_PAD, NGENE, RNK, RNK, EPI_NONE);
}